// round 3
// baseline (speedup 1.0000x reference)
#include <cuda_runtime.h>
#include <math.h>

// ---------------- problem dims ----------------
#define PXTOT 32768            // B*H*W = 8*64*64
#define NY    2097152          // PXTOT * 64
#define NH    4194304          // PXTOT * 128
#define NV4   (NY/4)
#define NITERS 32

// ---------------- device state ----------------
__device__ float g_buf0[NY];       // y / ytmp ping-pong
__device__ float g_buf1[NY];
__device__ float g_k[7][NY];
__device__ float g_h1[NH];
__device__ float g_h2[NH];
__device__ double g_sumsq[NITERS]; // per-iteration error accumulators
__device__ unsigned int g_bar;     // monotonic grid-barrier counter
__device__ unsigned int g_tk1, g_tk2, g_tk3;  // monotonic ticket counters

// ---------------- f32x2 helpers ----------------
__device__ __forceinline__ unsigned long long pk2(float lo, float hi) {
  unsigned long long r;
  asm("mov.b64 %0, {%1, %2};" : "=l"(r) : "f"(lo), "f"(hi));
  return r;
}
__device__ __forceinline__ unsigned long long dup2(float a) { return pk2(a, a); }
__device__ __forceinline__ unsigned long long fma2(unsigned long long a,
                                                   unsigned long long b,
                                                   unsigned long long c) {
  unsigned long long d;
  asm("fma.rn.f32x2 %0, %1, %2, %3;" : "=l"(d) : "l"(a), "l"(b), "l"(c));
  return d;
}
__device__ __forceinline__ void upk2(float& lo, float& hi, unsigned long long v) {
  asm("mov.b64 {%0, %1}, %2;" : "=f"(lo), "=f"(hi) : "l"(v));
}

// ---------------- init node (resets persistent counters each replay) ----------------
__global__ void init_k() {
  g_bar = 0u; g_tk1 = 0u; g_tk2 = 0u; g_tk3 = 0u;
  for (int i = 0; i < NITERS; i++) g_sumsq[i] = 0.0;
}

// ---------------- software grid barrier ----------------
__device__ __forceinline__ void gsync(unsigned int& bt, unsigned int nb) {
  __syncthreads();
  if (threadIdx.x == 0) {
    __threadfence();                       // release all block stores (gpu scope)
    atomicAdd(&g_bar, 1u);
    bt += nb;
    while ((int)(*(volatile unsigned int*)&g_bar - bt) < 0) __nanosleep(32);
    __threadfence();                       // acquire (CCTL.IVALL scrubs SM L1)
  }
  __syncthreads();
}

// ---------------- dynamic tile tickets ----------------
// Epoch invariant: every block performs its successes + exactly one failing grab,
// so each phase invocation consumes exactly (ntiles + nblocks) tickets.
__device__ __forceinline__ int grab(unsigned int* ctr, unsigned int base, int nt, int* s_t) {
  if (threadIdx.x == 0) {
    unsigned int tk = atomicAdd(ctr, 1u);
    int loc = (int)(tk - base);
    *s_t = (loc < nt) ? loc : -1;
  }
  __syncthreads();
  int r = *s_t;
  __syncthreads();
  return r;
}

// ---------------- conv1: 1x1, (64 + time) -> 128, relu, in -> g_h1 ----------------
// tile = 128 px x 128 f, 256 tiles. smem: in_s[32][132] @0, w_s[32][128] @4224
__device__ void conv1_phase(const float* __restrict__ in, float tval,
                            const float* __restrict__ w1, const float* __restrict__ b1,
                            float* s, unsigned int& ep, unsigned int nb, int* s_t) {
  float* in_s = s;
  float* w_s  = s + 4224;
  const int tid = threadIdx.x;
  const int f0  = (tid & 15) * 8;
  const int px0 = (tid >> 4) * 8;
  const float4* in4 = (const float4*)in;
  const float4* w14 = (const float4*)w1;
  while (true) {
    int tile = grab(&g_tk1, ep, 256, s_t);
    if (tile < 0) break;
    const int pxbase = tile * 128;
    float acc[8][8];
#pragma unroll
    for (int j = 0; j < 8; j++) {
      float b = b1[f0 + j] + tval * w1[f0 + j];   // row 0 of w1 = time channel
#pragma unroll
      for (int i = 0; i < 8; i++) acc[i][j] = b;
    }
    for (int ch = 0; ch < 64; ch += 32) {
      __syncthreads();
#pragma unroll
      for (int l = 0; l < 4; l++) {
        int idx = tid + l * 256;
        int px = idx >> 3, c4 = idx & 7;
        float4 v = in4[(size_t)(pxbase + px) * 16 + (ch >> 2) + c4];
        in_s[(c4*4+0)*132 + px] = v.x; in_s[(c4*4+1)*132 + px] = v.y;
        in_s[(c4*4+2)*132 + px] = v.z; in_s[(c4*4+3)*132 + px] = v.w;
      }
#pragma unroll
      for (int l = 0; l < 4; l++) {
        int idx = tid + l * 256;
        int k = idx >> 5, f4 = idx & 31;
        ((float4*)w_s)[k * 32 + f4] = w14[(size_t)(1 + ch + k) * 32 + f4];
      }
      __syncthreads();
#pragma unroll 4
      for (int k = 0; k < 32; k++) {
        float4 a0 = *(const float4*)&in_s[k*132 + px0];
        float4 a1 = *(const float4*)&in_s[k*132 + px0 + 4];
        float4 w0 = *(const float4*)&w_s[k*128 + f0];
        float4 w4 = *(const float4*)&w_s[k*128 + f0 + 4];
        float a[8] = {a0.x,a0.y,a0.z,a0.w,a1.x,a1.y,a1.z,a1.w};
        float w[8] = {w0.x,w0.y,w0.z,w0.w,w4.x,w4.y,w4.z,w4.w};
#pragma unroll
        for (int i = 0; i < 8; i++)
#pragma unroll
          for (int j = 0; j < 8; j++)
            acc[i][j] = fmaf(a[i], w[j], acc[i][j]);
      }
    }
    float4* out4 = (float4*)g_h1;
#pragma unroll
    for (int i = 0; i < 8; i++) {
      float4 o0 = make_float4(fmaxf(acc[i][0],0.f), fmaxf(acc[i][1],0.f),
                              fmaxf(acc[i][2],0.f), fmaxf(acc[i][3],0.f));
      float4 o1 = make_float4(fmaxf(acc[i][4],0.f), fmaxf(acc[i][5],0.f),
                              fmaxf(acc[i][6],0.f), fmaxf(acc[i][7],0.f));
      size_t base = (size_t)(pxbase + px0 + i) * 32 + (f0 >> 2);
      out4[base] = o0; out4[base + 1] = o1;
    }
    __syncthreads();
  }
  ep += 256 + nb;
}

// ---------------- conv2: 3x3 SAME, (128 + time) -> 128, relu, g_h1 -> g_h2 --------
// tile = one output row (64 px) x 128 f, 512 tiles. Packed f32x2 math.
// smem: in_s[3][66][8] @0 (1584), w_s[9][8][128] @1584 (9216), wt_s[9][128] @10800
__device__ void conv2_phase(float tval, const float* __restrict__ w2,
                            const float* __restrict__ b2,
                            float* s, unsigned int& ep, unsigned int nb, int* s_t) {
  float* in_s = s;
  float* w_s  = s + 1584;
  float* wt_s = s + 10800;
  const int tid = threadIdx.x;
  const int f0  = (tid & 15) * 8;
  const int px0 = (tid >> 4) * 4;
  const float4* w24 = (const float4*)w2;
  const float4* in4 = (const float4*)g_h1;
  const unsigned long long td = dup2(tval);
  while (true) {
    int blk = grab(&g_tk2, ep, 512, s_t);
    if (blk < 0) break;
    const int b = blk >> 6, oy = blk & 63;
    // time-channel weights (input channel 0 of each tap)
    for (int idx = tid; idx < 288; idx += 256) {
      int tap = idx >> 5, f4 = idx & 31;
      ((float4*)wt_s)[tap * 32 + f4] = w24[(size_t)tap * 129 * 32 + f4];
    }
    if (tid < 48) {   // zero halo columns (never rewritten in chunk loop)
      int r = tid >> 4, rem = tid & 15;
      int col = (rem < 8) ? 0 : 65, c = rem & 7;
      in_s[(r * 66 + col) * 8 + c] = 0.f;
    }
    unsigned long long acc[4][4];   // [px][f-pair]
    {
      float4 bv0 = ((const float4*)b2)[f0 >> 2];
      float4 bv1 = ((const float4*)b2)[(f0 >> 2) + 1];
      unsigned long long bp0 = pk2(bv0.x, bv0.y), bp1 = pk2(bv0.z, bv0.w);
      unsigned long long bp2 = pk2(bv1.x, bv1.y), bp3 = pk2(bv1.z, bv1.w);
#pragma unroll
      for (int i = 0; i < 4; i++) {
        acc[i][0] = bp0; acc[i][1] = bp1; acc[i][2] = bp2; acc[i][3] = bp3;
      }
    }
    __syncthreads();
    // time-channel contribution with border-valid tap masking
#pragma unroll
    for (int ky = 0; ky < 3; ky++) {
      int row = oy + ky - 1;
      if (row < 0 || row >= 64) continue;
#pragma unroll
      for (int kx = 0; kx < 3; kx++) {
        const float* wb = &wt_s[(ky * 3 + kx) * 128 + f0];
        ulonglong2 wA = *(const ulonglong2*)wb;
        ulonglong2 wB = *(const ulonglong2*)(wb + 4);
#pragma unroll
        for (int i = 0; i < 4; i++) {
          int col = px0 + i + kx - 1;
          if (col >= 0 && col < 64) {
            acc[i][0] = fma2(td, wA.x, acc[i][0]);
            acc[i][1] = fma2(td, wA.y, acc[i][1]);
            acc[i][2] = fma2(td, wB.x, acc[i][2]);
            acc[i][3] = fma2(td, wB.y, acc[i][3]);
          }
        }
      }
    }
    for (int ch = 0; ch < 128; ch += 8) {
      __syncthreads();
      // input halo tile: 3 rows x 64 px x 8 ch
      for (int idx = tid; idx < 384; idx += 256) {
        int ri = idx >> 7, rem = idx & 127, px = rem >> 1, q = rem & 1;
        int row = oy + ri - 1;
        float4 v = make_float4(0.f, 0.f, 0.f, 0.f);
        if (row >= 0 && row < 64)
          v = in4[((size_t)((b * 64 + row) * 64 + px)) * 32 + (ch >> 2) + q];
        *(float4*)&in_s[(ri * 66 + px + 1) * 8 + q * 4] = v;
      }
      // weights: 9 taps x 8 ch x 128 f
      for (int idx = tid; idx < 2304; idx += 256) {
        int tap = idx >> 8, rem = idx & 255, cc = rem >> 5, f4 = rem & 31;
        ((float4*)w_s)[(tap * 8 + cc) * 32 + f4] =
            w24[((size_t)tap * 129 + 1 + ch + cc) * 32 + f4];
      }
      __syncthreads();
      for (int cc = 0; cc < 8; cc++) {
#pragma unroll
        for (int ky = 0; ky < 3; ky++) {
          unsigned long long dv[6];
#pragma unroll
          for (int d = 0; d < 6; d++)
            dv[d] = dup2(in_s[(ky * 66 + px0 + d) * 8 + cc]);
#pragma unroll
          for (int kx = 0; kx < 3; kx++) {
            const float* wb = &w_s[((ky * 3 + kx) * 8 + cc) * 128 + f0];
            ulonglong2 wA = *(const ulonglong2*)wb;
            ulonglong2 wB = *(const ulonglong2*)(wb + 4);
#pragma unroll
            for (int i = 0; i < 4; i++) {
              unsigned long long a = dv[i + kx];
              acc[i][0] = fma2(a, wA.x, acc[i][0]);
              acc[i][1] = fma2(a, wA.y, acc[i][1]);
              acc[i][2] = fma2(a, wB.x, acc[i][2]);
              acc[i][3] = fma2(a, wB.y, acc[i][3]);
            }
          }
        }
      }
    }
    float4* out4 = (float4*)g_h2;
#pragma unroll
    for (int i = 0; i < 4; i++) {
      float o[8];
      upk2(o[0], o[1], acc[i][0]); upk2(o[2], o[3], acc[i][1]);
      upk2(o[4], o[5], acc[i][2]); upk2(o[6], o[7], acc[i][3]);
#pragma unroll
      for (int j = 0; j < 8; j++) o[j] = fmaxf(o[j], 0.f);
      size_t base = ((size_t)blk * 64 + px0 + i) * 32 + (f0 >> 2);
      out4[base]     = make_float4(o[0], o[1], o[2], o[3]);
      out4[base + 1] = make_float4(o[4], o[5], o[6], o[7]);
    }
    __syncthreads();
  }
  ep += 512 + nb;
}

// ---------------- conv3: 1x1, (128 + time) -> 64, g_h2 -> g_k[kout] --------------
// tile = 128 px x 64 f, 256 tiles. smem: in_s[32][132] @0, w_s[32][64] @4224
__device__ void conv3_phase(float tval, const float* __restrict__ w3,
                            const float* __restrict__ b3, int kout,
                            float* s, unsigned int& ep, unsigned int nb, int* s_t) {
  float* in_s = s;
  float* w_s  = s + 4224;
  const int tid = threadIdx.x;
  const int f0  = (tid & 15) * 4;
  const int px0 = (tid >> 4) * 8;
  const float4* in4 = (const float4*)g_h2;
  const float4* w34 = (const float4*)w3;
  while (true) {
    int tile = grab(&g_tk3, ep, 256, s_t);
    if (tile < 0) break;
    const int pxbase = tile * 128;
    float acc[8][4];
#pragma unroll
    for (int j = 0; j < 4; j++) {
      float b = b3[f0 + j] + tval * w3[f0 + j];
#pragma unroll
      for (int i = 0; i < 8; i++) acc[i][j] = b;
    }
    for (int ch = 0; ch < 128; ch += 32) {
      __syncthreads();
#pragma unroll
      for (int l = 0; l < 4; l++) {
        int idx = tid + l * 256;
        int px = idx >> 3, c4 = idx & 7;
        float4 v = in4[(size_t)(pxbase + px) * 32 + (ch >> 2) + c4];
        in_s[(c4*4+0)*132 + px] = v.x; in_s[(c4*4+1)*132 + px] = v.y;
        in_s[(c4*4+2)*132 + px] = v.z; in_s[(c4*4+3)*132 + px] = v.w;
      }
#pragma unroll
      for (int l = 0; l < 2; l++) {
        int idx = tid + l * 256;
        int k = idx >> 4, f4 = idx & 15;
        ((float4*)w_s)[k * 16 + f4] = w34[(size_t)(1 + ch + k) * 16 + f4];
      }
      __syncthreads();
#pragma unroll 4
      for (int k = 0; k < 32; k++) {
        float4 a0 = *(const float4*)&in_s[k*132 + px0];
        float4 a1 = *(const float4*)&in_s[k*132 + px0 + 4];
        float4 w0 = *(const float4*)&w_s[k*64 + f0];
        float a[8] = {a0.x,a0.y,a0.z,a0.w,a1.x,a1.y,a1.z,a1.w};
        float w[4] = {w0.x,w0.y,w0.z,w0.w};
#pragma unroll
        for (int i = 0; i < 8; i++)
#pragma unroll
          for (int j = 0; j < 4; j++)
            acc[i][j] = fmaf(a[i], w[j], acc[i][j]);
      }
    }
    float4* out4 = (float4*)&g_k[kout][0];
#pragma unroll
    for (int i = 0; i < 8; i++)
      out4[(size_t)(pxbase + px0 + i) * 16 + (f0 >> 2)] =
          make_float4(acc[i][0], acc[i][1], acc[i][2], acc[i][3]);
    __syncthreads();
  }
  ep += 256 + nb;
}

// ---------------- stage combine: yt = y + hs * sum(c_m * k[i_m]) ----------------
__device__ void combine_phase(float* yt, const float* y, float hs,
                              float c1, float c2, float c3, float c4, float c5,
                              int nk, int i1, int i2, int i3, int i4, int i5,
                              unsigned int nb) {
  const float4* y4 = (const float4*)y;
  float4* o4 = (float4*)yt;
  const float4* p1 = (const float4*)g_k[i1];
  const float4* p2 = (const float4*)g_k[i2];
  const float4* p3 = (const float4*)g_k[i3];
  const float4* p4 = (const float4*)g_k[i4];
  const float4* p5 = (const float4*)g_k[i5];
  for (int i = blockIdx.x * 256 + threadIdx.x; i < NV4; i += nb * 256) {
    float4 v = p1[i];
    float sx = c1*v.x, sy = c1*v.y, sz = c1*v.z, sw = c1*v.w;
    if (nk > 1) { v = p2[i]; sx += c2*v.x; sy += c2*v.y; sz += c2*v.z; sw += c2*v.w; }
    if (nk > 2) { v = p3[i]; sx += c3*v.x; sy += c3*v.y; sz += c3*v.z; sw += c3*v.w; }
    if (nk > 3) { v = p4[i]; sx += c4*v.x; sy += c4*v.y; sz += c4*v.z; sw += c4*v.w; }
    if (nk > 4) { v = p5[i]; sx += c5*v.x; sy += c5*v.y; sz += c5*v.z; sw += c5*v.w; }
    float4 yv = y4[i];
    o4[i] = make_float4(yv.x + hs*sx, yv.y + hs*sy, yv.z + hs*sz, yv.w + hs*sw);
  }
}

// ---------------- error norm partial reduce ----------------
__device__ void err_phase(const float* y, const float* y5, float hs, int it,
                          double* s_red, unsigned int nb) {
  const float E1f = (float)( 71.0 / 57600.0);
  const float E3f = (float)(-71.0 / 16695.0);
  const float E4f = (float)( 71.0 / 1920.0);
  const float E5f = (float)(-17253.0 / 339200.0);
  const float E6f = (float)( 22.0 / 525.0);
  const float E7f = (float)(-1.0 / 40.0);
  const float4* y4  = (const float4*)y;
  const float4* y54 = (const float4*)y5;
  const float4* k1 = (const float4*)g_k[0];
  const float4* k3 = (const float4*)g_k[2];
  const float4* k4 = (const float4*)g_k[3];
  const float4* k5 = (const float4*)g_k[4];
  const float4* k6 = (const float4*)g_k[5];
  const float4* k7 = (const float4*)g_k[6];
  double local = 0.0;
  for (int i = blockIdx.x * 256 + threadIdx.x; i < NV4; i += nb * 256) {
    float4 a = y4[i], b = y54[i];
    float4 v1 = k1[i], v3 = k3[i], v4 = k4[i], v5 = k5[i], v6 = k6[i], v7 = k7[i];
#define ECOMP(c) { \
    float e = hs * (E1f*v1.c + E3f*v3.c + E4f*v4.c + E5f*v5.c + E6f*v6.c + E7f*v7.c); \
    float sc = 1e-3f + 1e-3f * fmaxf(fabsf(a.c), fabsf(b.c)); \
    float r = e / sc; local += (double)r * (double)r; }
    ECOMP(x) ECOMP(y) ECOMP(z) ECOMP(w)
#undef ECOMP
  }
  int tid = threadIdx.x;
  __syncthreads();
  s_red[tid] = local;
  __syncthreads();
  for (int o = 128; o > 0; o >>= 1) {
    if (tid < o) s_red[tid] += s_red[tid + o];
    __syncthreads();
  }
  if (tid == 0) atomicAdd(&g_sumsq[it], s_red[0]);
}

// ---------------- output head: 1x1, 64 -> 10 ----------------
__device__ void head_phase(const float* __restrict__ y, const float* __restrict__ wo,
                           const float* __restrict__ bo, float* __restrict__ out,
                           float* s, unsigned int nb) {
  float* w_s = s;        // [64][10]
  float* b_s = s + 640;
  int tid = threadIdx.x;
  __syncthreads();
  for (int i = tid; i < 640; i += 256) w_s[i] = wo[i];
  if (tid < 10) b_s[tid] = bo[tid];
  __syncthreads();
  for (int p = blockIdx.x * 256 + tid; p < PXTOT; p += nb * 256) {
    const float4* yp = (const float4*)(y + (size_t)p * 64);
    float o[10];
#pragma unroll
    for (int k = 0; k < 10; k++) o[k] = b_s[k];
#pragma unroll 4
    for (int c4 = 0; c4 < 16; c4++) {
      float4 v = yp[c4];
      int c = c4 * 4;
#pragma unroll
      for (int k = 0; k < 10; k++)
        o[k] += v.x * w_s[c*10+k] + v.y * w_s[(c+1)*10+k] +
                v.z * w_s[(c+2)*10+k] + v.w * w_s[(c+3)*10+k];
    }
#pragma unroll
    for (int k = 0; k < 10; k++) out[(size_t)p * 10 + k] = o[k];
  }
}

// ---------------- the persistent ODE kernel ----------------
__global__ void __launch_bounds__(256, 1)
ode_k(const float* __restrict__ x,
      const float* __restrict__ w1, const float* __restrict__ b1,
      const float* __restrict__ w2, const float* __restrict__ b2,
      const float* __restrict__ w3, const float* __restrict__ b3,
      const float* __restrict__ wo, const float* __restrict__ bo,
      float* __restrict__ out) {
  extern __shared__ float s_mem[];
  __shared__ double s_red[256];
  __shared__ int s_t;
  const unsigned int nb = gridDim.x;
  unsigned int bt = 0;                 // barrier target (thread0-meaningful)
  unsigned int e1 = 0, e2 = 0, e3 = 0; // ticket epoch bases

  // dopri5 tableau
  const float A21 = (float)(1.0/5.0);
  const float A31 = (float)(3.0/40.0),  A32 = (float)(9.0/40.0);
  const float A41 = (float)(44.0/45.0), A42 = (float)(-56.0/15.0), A43 = (float)(32.0/9.0);
  const float A51 = (float)(19372.0/6561.0), A52 = (float)(-25360.0/2187.0),
              A53 = (float)(64448.0/6561.0), A54 = (float)(-212.0/729.0);
  const float A61 = (float)(9017.0/3168.0), A62 = (float)(-355.0/33.0),
              A63 = (float)(46732.0/5247.0), A64 = (float)(49.0/176.0),
              A65 = (float)(-5103.0/18656.0);
  const float Bc1 = (float)(35.0/384.0), Bc3 = (float)(500.0/1113.0),
              Bc4 = (float)(125.0/192.0), Bc5 = (float)(-2187.0/6784.0),
              Bc6 = (float)(11.0/84.0);

  // y0 = x
  {
    float4* d = (float4*)g_buf0;
    const float4* sx = (const float4*)x;
    for (int i = blockIdx.x * 256 + threadIdx.x; i < NV4; i += nb * 256) d[i] = sx[i];
  }
  gsync(bt, nb);

  float t = 0.0f, h = 0.1f;
  int cur = 0;   // 0: y=buf0, 1: y=buf1

#define FEVAL(SRC, TV, KO)                                              \
  do {                                                                  \
    conv1_phase((SRC), (TV), w1, b1, s_mem, e1, nb, &s_t); gsync(bt, nb); \
    conv2_phase((TV), w2, b2, s_mem, e2, nb, &s_t);        gsync(bt, nb); \
    conv3_phase((TV), w3, b3, (KO), s_mem, e3, nb, &s_t);  gsync(bt, nb); \
  } while (0)

  for (int it = 0; it < NITERS; it++) {
    if (t >= 1.0f) break;        // uniform across all blocks (replicated controller)
    float* y  = cur ? g_buf1 : g_buf0;
    float* yt = cur ? g_buf0 : g_buf1;
    const float hs = fminf(h, 1.0f - t);
    const float t2 = t + hs * 0.2f;
    const float t3 = t + hs * 0.3f;
    const float t4 = t + hs * 0.8f;
    const float t5 = t + hs * (8.0f / 9.0f);
    const float t6 = t + hs;

    FEVAL(y, t, 0);                                                   // k1
    combine_phase(yt, y, hs, A21,0,0,0,0, 1, 0,0,0,0,0, nb); gsync(bt, nb);
    FEVAL(yt, t2, 1);                                                 // k2
    combine_phase(yt, y, hs, A31,A32,0,0,0, 2, 0,1,0,0,0, nb); gsync(bt, nb);
    FEVAL(yt, t3, 2);                                                 // k3
    combine_phase(yt, y, hs, A41,A42,A43,0,0, 3, 0,1,2,0,0, nb); gsync(bt, nb);
    FEVAL(yt, t4, 3);                                                 // k4
    combine_phase(yt, y, hs, A51,A52,A53,A54,0, 4, 0,1,2,3,0, nb); gsync(bt, nb);
    FEVAL(yt, t5, 4);                                                 // k5
    combine_phase(yt, y, hs, A61,A62,A63,A64,A65, 5, 0,1,2,3,4, nb); gsync(bt, nb);
    FEVAL(yt, t6, 5);                                                 // k6
    combine_phase(yt, y, hs, Bc1,Bc3,Bc4,Bc5,Bc6, 5, 0,2,3,4,5, nb); gsync(bt, nb);  // y5
    FEVAL(yt, t6, 6);                                                 // k7 = f(t+hs, y5)

    err_phase(y, yt, hs, it, s_red, nb);
    gsync(bt, nb);

    // replicated controller (identical fp ops -> identical values in every thread)
    double ss = g_sumsq[it];
    float en = sqrtf((float)(ss / (double)NY));
    int accept = (en <= 1.0f) ? 1 : 0;
    float ens = fmaxf(en, 1e-8f);
    float fac = fminf(fmaxf(0.9f * powf(ens, -0.2f), 0.2f), 10.0f);
    if (accept) { t = t + hs; cur ^= 1; }   // pointer-swap instead of copy
    h = fmaxf(hs * fac, 1e-4f);
  }
#undef FEVAL

  const float* yfin = cur ? g_buf1 : g_buf0;
  head_phase(yfin, wo, bo, out, s_mem, nb);
}

// ---------------- launch: 2 graph nodes total ----------------
extern "C" void kernel_launch(void* const* d_in, const int* in_sizes, int n_in,
                              void* d_out, int out_size) {
  (void)in_sizes; (void)n_in; (void)out_size;
  const float* x  = (const float*)d_in[0];
  const float* w1 = (const float*)d_in[1];
  const float* b1 = (const float*)d_in[2];
  const float* w2 = (const float*)d_in[3];
  const float* b2 = (const float*)d_in[4];
  const float* w3 = (const float*)d_in[5];
  const float* b3 = (const float*)d_in[6];
  const float* wo = (const float*)d_in[7];
  const float* bo = (const float*)d_in[8];

  int dev = 0;
  cudaGetDevice(&dev);
  int nsm = 148;
  cudaDeviceGetAttribute(&nsm, cudaDevAttrMultiProcessorCount, dev);

  const int smem_bytes = 11952 * 4;   // conv2 region is the union max (47808 B)
  cudaFuncSetAttribute(ode_k, cudaFuncAttributeMaxDynamicSharedMemorySize, smem_bytes);

  init_k<<<1, 1>>>();
  ode_k<<<nsm, 256, smem_bytes>>>(x, w1, b1, w2, b2, w3, b3, wo, bo, (float*)d_out);
}

// round 6
// speedup vs baseline: 1.5723x; 1.5723x over previous
#include <cuda_runtime.h>
#include <math.h>

// ---------------- problem dims ----------------
#define PXTOT 32768            // B*H*W = 8*64*64
#define NY    2097152          // PXTOT * 64
#define NH    4194304          // PXTOT * 128
#define NV4   (NY/4)
#define NITERS 32

// ---------------- device state ----------------
__device__ float g_buf0[NY];       // y / ytmp ping-pong
__device__ float g_buf1[NY];
__device__ float g_k[7][NY];       // k7 slot unused now (kept for layout simplicity)
__device__ float g_h1[NH];
__device__ float g_h2[NH];
__device__ double g_sumsq[NITERS];
__device__ unsigned int g_bar;
__device__ unsigned int g_tk1, g_tk2, g_tk3;

// ---------------- f32x2 helpers ----------------
__device__ __forceinline__ unsigned long long pk2(float lo, float hi) {
  unsigned long long r;
  asm("mov.b64 %0, {%1, %2};" : "=l"(r) : "f"(lo), "f"(hi));
  return r;
}
__device__ __forceinline__ unsigned long long dup2(float a) { return pk2(a, a); }
__device__ __forceinline__ unsigned long long fma2(unsigned long long a,
                                                   unsigned long long b,
                                                   unsigned long long c) {
  unsigned long long d;
  asm("fma.rn.f32x2 %0, %1, %2, %3;" : "=l"(d) : "l"(a), "l"(b), "l"(c));
  return d;
}
__device__ __forceinline__ void upk2(float& lo, float& hi, unsigned long long v) {
  asm("mov.b64 {%0, %1}, %2;" : "=f"(lo), "=f"(hi) : "l"(v));
}

// ---------------- init node ----------------
__global__ void init_k() {
  g_bar = 0u; g_tk1 = 0u; g_tk2 = 0u; g_tk3 = 0u;
  for (int i = 0; i < NITERS; i++) g_sumsq[i] = 0.0;
}

// ---------------- software grid barrier ----------------
__device__ __forceinline__ void gsync(unsigned int& bt, unsigned int nb) {
  __syncthreads();
  if (threadIdx.x == 0) {
    __threadfence();
    atomicAdd(&g_bar, 1u);
    bt += nb;
    while ((int)(*(volatile unsigned int*)&g_bar - bt) < 0) __nanosleep(32);
    __threadfence();
  }
  __syncthreads();
}

// ---------------- dynamic tile tickets ----------------
__device__ __forceinline__ int grab(unsigned int* ctr, unsigned int base, int nt, int* s_t) {
  if (threadIdx.x == 0) {
    unsigned int tk = atomicAdd(ctr, 1u);
    int loc = (int)(tk - base);
    *s_t = (loc < nt) ? loc : -1;
  }
  __syncthreads();
  int r = *s_t;
  __syncthreads();
  return r;
}

// ---------------- conv1: 1x1, (64 + time) -> 128, relu, in -> g_h1 ----------------
// tile = 128 px x 128 f, 256 tiles. smem: in_s[32][132] @0, w_s[32][128] @4224
__device__ void conv1_phase(const float* __restrict__ in, float tval,
                            const float* __restrict__ w1, const float* __restrict__ b1,
                            float* s, unsigned int& ep, unsigned int nb, int* s_t) {
  float* in_s = s;
  float* w_s  = s + 4224;
  const int tid = threadIdx.x;
  const int f0  = (tid & 15) * 8;
  const int px0 = (tid >> 4) * 8;
  const float4* in4 = (const float4*)in;
  const float4* w14 = (const float4*)w1;
  while (true) {
    int tile = grab(&g_tk1, ep, 256, s_t);
    if (tile < 0) break;
    const int pxbase = tile * 128;
    float acc[8][8];
#pragma unroll
    for (int j = 0; j < 8; j++) {
      float b = b1[f0 + j] + tval * w1[f0 + j];   // row 0 of w1 = time channel
#pragma unroll
      for (int i = 0; i < 8; i++) acc[i][j] = b;
    }
    for (int ch = 0; ch < 64; ch += 32) {
      __syncthreads();
#pragma unroll
      for (int l = 0; l < 4; l++) {
        int idx = tid + l * 256;
        int px = idx >> 3, c4 = idx & 7;
        float4 v = in4[(size_t)(pxbase + px) * 16 + (ch >> 2) + c4];
        in_s[(c4*4+0)*132 + px] = v.x; in_s[(c4*4+1)*132 + px] = v.y;
        in_s[(c4*4+2)*132 + px] = v.z; in_s[(c4*4+3)*132 + px] = v.w;
      }
#pragma unroll
      for (int l = 0; l < 4; l++) {
        int idx = tid + l * 256;
        int k = idx >> 5, f4 = idx & 31;
        ((float4*)w_s)[k * 32 + f4] = w14[(size_t)(1 + ch + k) * 32 + f4];
      }
      __syncthreads();
#pragma unroll 4
      for (int k = 0; k < 32; k++) {
        float4 a0 = *(const float4*)&in_s[k*132 + px0];
        float4 a1 = *(const float4*)&in_s[k*132 + px0 + 4];
        float4 w0 = *(const float4*)&w_s[k*128 + f0];
        float4 w4 = *(const float4*)&w_s[k*128 + f0 + 4];
        float a[8] = {a0.x,a0.y,a0.z,a0.w,a1.x,a1.y,a1.z,a1.w};
        float w[8] = {w0.x,w0.y,w0.z,w0.w,w4.x,w4.y,w4.z,w4.w};
#pragma unroll
        for (int i = 0; i < 8; i++)
#pragma unroll
          for (int j = 0; j < 8; j++)
            acc[i][j] = fmaf(a[i], w[j], acc[i][j]);
      }
    }
    float4* out4 = (float4*)g_h1;
#pragma unroll
    for (int i = 0; i < 8; i++) {
      float4 o0 = make_float4(fmaxf(acc[i][0],0.f), fmaxf(acc[i][1],0.f),
                              fmaxf(acc[i][2],0.f), fmaxf(acc[i][3],0.f));
      float4 o1 = make_float4(fmaxf(acc[i][4],0.f), fmaxf(acc[i][5],0.f),
                              fmaxf(acc[i][6],0.f), fmaxf(acc[i][7],0.f));
      size_t base = (size_t)(pxbase + px0 + i) * 32 + (f0 >> 2);
      out4[base] = o0; out4[base + 1] = o1;
    }
    __syncthreads();
  }
  ep += 256 + nb;
}

// ---------------- conv2: 3x3 SAME, (128 + time) -> 128, relu, g_h1 -> g_h2 --------
// tile = TWO output rows (128 px) x 128 f, 256 tiles. Packed f32x2 math.
// Per-thread tile: 2 rows x 4 px x 8 f. Weight smem loads amortize over both rows.
// smem: in_s[4][66][8] @0 (2112), w_s[9][8][128] @2112 (9216), wt_s[9][128] @11328
__device__ void conv2_phase(float tval, const float* __restrict__ w2,
                            const float* __restrict__ b2,
                            float* s, unsigned int& ep, unsigned int nb, int* s_t) {
  float* in_s = s;
  float* w_s  = s + 2112;
  float* wt_s = s + 11328;
  const int tid = threadIdx.x;
  const int f0  = (tid & 15) * 8;
  const int px0 = (tid >> 4) * 4;
  const float4* w24 = (const float4*)w2;
  const float4* in4 = (const float4*)g_h1;
  const unsigned long long td = dup2(tval);
  while (true) {
    int blk = grab(&g_tk2, ep, 256, s_t);
    if (blk < 0) break;
    const int b   = blk >> 5;
    const int oy0 = (blk & 31) * 2;           // output rows oy0, oy0+1
    // time-channel weights (input channel 0 of each tap)
    for (int idx = tid; idx < 288; idx += 256) {
      int tap = idx >> 5, f4 = idx & 31;
      ((float4*)wt_s)[tap * 32 + f4] = w24[(size_t)tap * 129 * 32 + f4];
    }
    if (tid < 64) {   // zero halo columns of all 4 input rows
      int r = tid >> 4, rem = tid & 15;
      int col = (rem < 8) ? 0 : 65, c = rem & 7;
      in_s[(r * 66 + col) * 8 + c] = 0.f;
    }
    unsigned long long acc[2][4][4];   // [row][px][f-pair]
    {
      float4 bv0 = ((const float4*)b2)[f0 >> 2];
      float4 bv1 = ((const float4*)b2)[(f0 >> 2) + 1];
      unsigned long long bp0 = pk2(bv0.x, bv0.y), bp1 = pk2(bv0.z, bv0.w);
      unsigned long long bp2 = pk2(bv1.x, bv1.y), bp3 = pk2(bv1.z, bv1.w);
#pragma unroll
      for (int r = 0; r < 2; r++)
#pragma unroll
        for (int i = 0; i < 4; i++) {
          acc[r][i][0] = bp0; acc[r][i][1] = bp1;
          acc[r][i][2] = bp2; acc[r][i][3] = bp3;
        }
    }
    __syncthreads();
    // time-channel contribution with border-valid tap masking
#pragma unroll
    for (int ky = 0; ky < 3; ky++) {
#pragma unroll
      for (int kx = 0; kx < 3; kx++) {
        const float* wb = &wt_s[(ky * 3 + kx) * 128 + f0];
        ulonglong2 wA = *(const ulonglong2*)wb;
        ulonglong2 wB = *(const ulonglong2*)(wb + 4);
#pragma unroll
        for (int r = 0; r < 2; r++) {
          int grow = oy0 + r + ky - 1;
          if (grow >= 0 && grow < 64) {
#pragma unroll
            for (int i = 0; i < 4; i++) {
              int col = px0 + i + kx - 1;
              if (col >= 0 && col < 64) {
                acc[r][i][0] = fma2(td, wA.x, acc[r][i][0]);
                acc[r][i][1] = fma2(td, wA.y, acc[r][i][1]);
                acc[r][i][2] = fma2(td, wB.x, acc[r][i][2]);
                acc[r][i][3] = fma2(td, wB.y, acc[r][i][3]);
              }
            }
          }
        }
      }
    }
    for (int ch = 0; ch < 128; ch += 8) {
      __syncthreads();
      // input tile: 4 rows (oy0-1..oy0+2) x 64 px x 8 ch = 512 float4
#pragma unroll
      for (int l = 0; l < 2; l++) {
        int idx = tid + l * 256;
        int ri = idx >> 7, rem = idx & 127, px = rem >> 1, q = rem & 1;
        int row = oy0 + ri - 1;
        float4 v = make_float4(0.f, 0.f, 0.f, 0.f);
        if (row >= 0 && row < 64)
          v = in4[((size_t)((b * 64 + row) * 64 + px)) * 32 + (ch >> 2) + q];
        *(float4*)&in_s[(ri * 66 + px + 1) * 8 + q * 4] = v;
      }
      // weights: 9 taps x 8 ch x 128 f = 2304 float4
      for (int idx = tid; idx < 2304; idx += 256) {
        int tap = idx >> 8, rem = idx & 255, cc = rem >> 5, f4 = rem & 31;
        ((float4*)w_s)[(tap * 8 + cc) * 32 + f4] =
            w24[((size_t)tap * 129 + 1 + ch + cc) * 32 + f4];
      }
      __syncthreads();
      for (int cc = 0; cc < 8; cc++) {
        unsigned long long dv[4][6];
#pragma unroll
        for (int ri = 0; ri < 4; ri++)
#pragma unroll
          for (int d = 0; d < 6; d++)
            dv[ri][d] = dup2(in_s[(ri * 66 + px0 + d) * 8 + cc]);
#pragma unroll
        for (int ky = 0; ky < 3; ky++) {
#pragma unroll
          for (int kx = 0; kx < 3; kx++) {
            const float* wb = &w_s[((ky * 3 + kx) * 8 + cc) * 128 + f0];
            ulonglong2 wA = *(const ulonglong2*)wb;
            ulonglong2 wB = *(const ulonglong2*)(wb + 4);
#pragma unroll
            for (int r = 0; r < 2; r++) {
#pragma unroll
              for (int i = 0; i < 4; i++) {
                unsigned long long a = dv[r + ky][i + kx];
                acc[r][i][0] = fma2(a, wA.x, acc[r][i][0]);
                acc[r][i][1] = fma2(a, wA.y, acc[r][i][1]);
                acc[r][i][2] = fma2(a, wB.x, acc[r][i][2]);
                acc[r][i][3] = fma2(a, wB.y, acc[r][i][3]);
              }
            }
          }
        }
      }
    }
    float4* out4 = (float4*)g_h2;
#pragma unroll
    for (int r = 0; r < 2; r++) {
#pragma unroll
      for (int i = 0; i < 4; i++) {
        float o[8];
        upk2(o[0], o[1], acc[r][i][0]); upk2(o[2], o[3], acc[r][i][1]);
        upk2(o[4], o[5], acc[r][i][2]); upk2(o[6], o[7], acc[r][i][3]);
#pragma unroll
        for (int j = 0; j < 8; j++) o[j] = fmaxf(o[j], 0.f);
        size_t px = (size_t)((b * 64 + oy0 + r) * 64 + px0 + i);
        size_t base = px * 32 + (f0 >> 2);
        out4[base]     = make_float4(o[0], o[1], o[2], o[3]);
        out4[base + 1] = make_float4(o[4], o[5], o[6], o[7]);
      }
    }
    __syncthreads();
  }
  ep += 256 + nb;
}

// ---------------- conv3 + fused combine / error ----------------
// tile = 128 px x 64 f, 256 tiles. smem: in_s[32][132] @0, w_s[32][64] @4224
// mode 0: store k[kout]; yt = y + hs*(sum cl_m*kl_m + cacc*k_new)
// mode 1: error stage (k7): no store; accumulate sum((err/scale)^2)
__device__ void conv3_phase(float tval, const float* __restrict__ w3,
                            const float* __restrict__ b3, int kout, int mode,
                            const float* kl0, const float* kl1,
                            const float* kl2, const float* kl3,
                            float cl0, float cl1, float cl2, float cl3,
                            int nload, float cacc,
                            const float* __restrict__ y, float* __restrict__ yt,
                            float hs, int it,
                            float* s, double* s_red,
                            unsigned int& ep, unsigned int nb, int* s_t) {
  float* in_s = s;
  float* w_s  = s + 4224;
  const int tid = threadIdx.x;
  const int f0  = (tid & 15) * 4;
  const int px0 = (tid >> 4) * 8;
  const float4* in4 = (const float4*)g_h2;
  const float4* w34 = (const float4*)w3;
  const float4* y4  = (const float4*)y;
  float4* yt4 = (float4*)yt;
  const float4* p0 = (const float4*)kl0;
  const float4* p1 = (const float4*)kl1;
  const float4* p2 = (const float4*)kl2;
  const float4* p3 = (const float4*)kl3;
  double local = 0.0;
  while (true) {
    int tile = grab(&g_tk3, ep, 256, s_t);
    if (tile < 0) break;
    const int pxbase = tile * 128;
    float acc[8][4];
#pragma unroll
    for (int j = 0; j < 4; j++) {
      float b = b3[f0 + j] + tval * w3[f0 + j];
#pragma unroll
      for (int i = 0; i < 8; i++) acc[i][j] = b;
    }
    for (int ch = 0; ch < 128; ch += 32) {
      __syncthreads();
#pragma unroll
      for (int l = 0; l < 4; l++) {
        int idx = tid + l * 256;
        int px = idx >> 3, c4 = idx & 7;
        float4 v = in4[(size_t)(pxbase + px) * 32 + (ch >> 2) + c4];
        in_s[(c4*4+0)*132 + px] = v.x; in_s[(c4*4+1)*132 + px] = v.y;
        in_s[(c4*4+2)*132 + px] = v.z; in_s[(c4*4+3)*132 + px] = v.w;
      }
#pragma unroll
      for (int l = 0; l < 2; l++) {
        int idx = tid + l * 256;
        int k = idx >> 4, f4 = idx & 15;
        ((float4*)w_s)[k * 16 + f4] = w34[(size_t)(1 + ch + k) * 16 + f4];
      }
      __syncthreads();
#pragma unroll 4
      for (int k = 0; k < 32; k++) {
        float4 a0 = *(const float4*)&in_s[k*132 + px0];
        float4 a1 = *(const float4*)&in_s[k*132 + px0 + 4];
        float4 w0 = *(const float4*)&w_s[k*64 + f0];
        float a[8] = {a0.x,a0.y,a0.z,a0.w,a1.x,a1.y,a1.z,a1.w};
        float w[4] = {w0.x,w0.y,w0.z,w0.w};
#pragma unroll
        for (int i = 0; i < 8; i++)
#pragma unroll
          for (int j = 0; j < 4; j++)
            acc[i][j] = fmaf(a[i], w[j], acc[i][j]);
      }
    }
    if (mode == 0) {
      float4* out4 = (float4*)&g_k[kout][0];
#pragma unroll
      for (int i = 0; i < 8; i++) {
        size_t off = (size_t)(pxbase + px0 + i) * 16 + (f0 >> 2);
        float4 kv = make_float4(acc[i][0], acc[i][1], acc[i][2], acc[i][3]);
        out4[off] = kv;
        float sx = 0.f, sy = 0.f, sz = 0.f, sw = 0.f;
        if (nload > 0) { float4 v = p0[off]; sx = fmaf(cl0,v.x,sx); sy = fmaf(cl0,v.y,sy); sz = fmaf(cl0,v.z,sz); sw = fmaf(cl0,v.w,sw); }
        if (nload > 1) { float4 v = p1[off]; sx = fmaf(cl1,v.x,sx); sy = fmaf(cl1,v.y,sy); sz = fmaf(cl1,v.z,sz); sw = fmaf(cl1,v.w,sw); }
        if (nload > 2) { float4 v = p2[off]; sx = fmaf(cl2,v.x,sx); sy = fmaf(cl2,v.y,sy); sz = fmaf(cl2,v.z,sz); sw = fmaf(cl2,v.w,sw); }
        if (nload > 3) { float4 v = p3[off]; sx = fmaf(cl3,v.x,sx); sy = fmaf(cl3,v.y,sy); sz = fmaf(cl3,v.z,sz); sw = fmaf(cl3,v.w,sw); }
        sx = fmaf(cacc, kv.x, sx); sy = fmaf(cacc, kv.y, sy);
        sz = fmaf(cacc, kv.z, sz); sw = fmaf(cacc, kv.w, sw);
        float4 yv = y4[off];
        yt4[off] = make_float4(fmaf(hs,sx,yv.x), fmaf(hs,sy,yv.y),
                               fmaf(hs,sz,yv.z), fmaf(hs,sw,yv.w));
      }
    } else {
      const float E1f = (float)( 71.0 / 57600.0);
      const float E3f = (float)(-71.0 / 16695.0);
      const float E4f = (float)( 71.0 / 1920.0);
      const float E5f = (float)(-17253.0 / 339200.0);
      const float E6f = (float)( 22.0 / 525.0);
      const float E7f = (float)(-1.0 / 40.0);
      const float4* k1 = (const float4*)g_k[0];
      const float4* k3 = (const float4*)g_k[2];
      const float4* k4 = (const float4*)g_k[3];
      const float4* k5 = (const float4*)g_k[4];
      const float4* k6 = (const float4*)g_k[5];
#pragma unroll
      for (int i = 0; i < 8; i++) {
        size_t off = (size_t)(pxbase + px0 + i) * 16 + (f0 >> 2);
        float4 v1 = k1[off], v3 = k3[off], v4 = k4[off], v5 = k5[off], v6 = k6[off];
        float4 a = y4[off], bb = yt4[off];   // yt holds y5
#define ECOMP(c, kacc) { \
        float e = hs * (E1f*v1.c + E3f*v3.c + E4f*v4.c + E5f*v5.c + E6f*v6.c + E7f*(kacc)); \
        float sc = 1e-3f + 1e-3f * fmaxf(fabsf(a.c), fabsf(bb.c)); \
        float r = e / sc; local += (double)r * (double)r; }
        ECOMP(x, acc[i][0]) ECOMP(y, acc[i][1]) ECOMP(z, acc[i][2]) ECOMP(w, acc[i][3])
#undef ECOMP
      }
    }
    __syncthreads();
  }
  ep += 256 + nb;
  if (mode == 1) {
    __syncthreads();
    s_red[tid] = local;
    __syncthreads();
    for (int o = 128; o > 0; o >>= 1) {
      if (tid < o) s_red[tid] += s_red[tid + o];
      __syncthreads();
    }
    if (tid == 0) atomicAdd(&g_sumsq[it], s_red[0]);
  }
}

// ---------------- output head: 1x1, 64 -> 10 ----------------
__device__ void head_phase(const float* __restrict__ y, const float* __restrict__ wo,
                           const float* __restrict__ bo, float* __restrict__ out,
                           float* s, unsigned int nb) {
  float* w_s = s;        // [64][10]
  float* b_s = s + 640;
  int tid = threadIdx.x;
  __syncthreads();
  for (int i = tid; i < 640; i += 256) w_s[i] = wo[i];
  if (tid < 10) b_s[tid] = bo[tid];
  __syncthreads();
  for (int p = blockIdx.x * 256 + tid; p < PXTOT; p += nb * 256) {
    const float4* yp = (const float4*)(y + (size_t)p * 64);
    float o[10];
#pragma unroll
    for (int k = 0; k < 10; k++) o[k] = b_s[k];
#pragma unroll 4
    for (int c4 = 0; c4 < 16; c4++) {
      float4 v = yp[c4];
      int c = c4 * 4;
#pragma unroll
      for (int k = 0; k < 10; k++)
        o[k] += v.x * w_s[c*10+k] + v.y * w_s[(c+1)*10+k] +
                v.z * w_s[(c+2)*10+k] + v.w * w_s[(c+3)*10+k];
    }
#pragma unroll
    for (int k = 0; k < 10; k++) out[(size_t)p * 10 + k] = o[k];
  }
}

// ---------------- the persistent ODE kernel ----------------
__global__ void __launch_bounds__(256, 1)
ode_k(const float* __restrict__ x,
      const float* __restrict__ w1, const float* __restrict__ b1,
      const float* __restrict__ w2, const float* __restrict__ b2,
      const float* __restrict__ w3, const float* __restrict__ b3,
      const float* __restrict__ wo, const float* __restrict__ bo,
      float* __restrict__ out) {
  extern __shared__ float s_mem[];
  __shared__ double s_red[256];
  __shared__ int s_t;
  const unsigned int nb = gridDim.x;
  unsigned int bt = 0;
  unsigned int e1 = 0, e2 = 0, e3 = 0;

  const float A21 = (float)(1.0/5.0);
  const float A31 = (float)(3.0/40.0),  A32 = (float)(9.0/40.0);
  const float A41 = (float)(44.0/45.0), A42 = (float)(-56.0/15.0), A43 = (float)(32.0/9.0);
  const float A51 = (float)(19372.0/6561.0), A52 = (float)(-25360.0/2187.0),
              A53 = (float)(64448.0/6561.0), A54 = (float)(-212.0/729.0);
  const float A61 = (float)(9017.0/3168.0), A62 = (float)(-355.0/33.0),
              A63 = (float)(46732.0/5247.0), A64 = (float)(49.0/176.0),
              A65 = (float)(-5103.0/18656.0);
  const float Bc1 = (float)(35.0/384.0), Bc3 = (float)(500.0/1113.0),
              Bc4 = (float)(125.0/192.0), Bc5 = (float)(-2187.0/6784.0),
              Bc6 = (float)(11.0/84.0);

  // y0 = x
  {
    float4* d = (float4*)g_buf0;
    const float4* sx = (const float4*)x;
    for (int i = blockIdx.x * 256 + threadIdx.x; i < NV4; i += nb * 256) d[i] = sx[i];
  }
  gsync(bt, nb);

  float t = 0.0f, h = 0.1f;
  int cur = 0;

  for (int it = 0; it < NITERS; it++) {
    if (t >= 1.0f) break;       // uniform across all blocks (replicated controller)
    float* y  = cur ? g_buf1 : g_buf0;
    float* yt = cur ? g_buf0 : g_buf1;
    const float hs = fminf(h, 1.0f - t);
    const float t2 = t + hs * 0.2f;
    const float t3 = t + hs * 0.3f;
    const float t4 = t + hs * 0.8f;
    const float t5 = t + hs * (8.0f / 9.0f);
    const float t6 = t + hs;

#define FEVAL(SRC, TV, KO, MODE, P0, P1, P2, P3, C0, C1, C2, C3, NL, CACC)      \
    do {                                                                        \
      conv1_phase((SRC), (TV), w1, b1, s_mem, e1, nb, &s_t); gsync(bt, nb);     \
      conv2_phase((TV), w2, b2, s_mem, e2, nb, &s_t);        gsync(bt, nb);     \
      conv3_phase((TV), w3, b3, (KO), (MODE), (P0), (P1), (P2), (P3),           \
                  (C0), (C1), (C2), (C3), (NL), (CACC), y, yt, hs, it,          \
                  s_mem, s_red, e3, nb, &s_t);               gsync(bt, nb);     \
    } while (0)

    // k1 .. k6 with fused combine producing the next stage input (yt)
    FEVAL(y,  t,  0, 0, g_k[0], g_k[0], g_k[0], g_k[0], 0,0,0,0,       0, A21);
    FEVAL(yt, t2, 1, 0, g_k[0], g_k[0], g_k[0], g_k[0], A31,0,0,0,     1, A32);
    FEVAL(yt, t3, 2, 0, g_k[0], g_k[1], g_k[0], g_k[0], A41,A42,0,0,   2, A43);
    FEVAL(yt, t4, 3, 0, g_k[0], g_k[1], g_k[2], g_k[0], A51,A52,A53,0, 3, A54);
    FEVAL(yt, t5, 4, 0, g_k[0], g_k[1], g_k[2], g_k[3], A61,A62,A63,A64, 4, A65);
    // k6 stage: fused combine produces y5 in yt (B weights; skips k2)
    FEVAL(yt, t6, 5, 0, g_k[0], g_k[2], g_k[3], g_k[4], Bc1,Bc3,Bc4,Bc5, 4, Bc6);
    // k7 stage: fused error norm (k7 never stored)
    FEVAL(yt, t6, 6, 1, g_k[0], g_k[0], g_k[0], g_k[0], 0,0,0,0,       0, 0.f);
#undef FEVAL

    // replicated controller
    double ss = g_sumsq[it];
    float en = sqrtf((float)(ss / (double)NY));
    int accept = (en <= 1.0f) ? 1 : 0;
    float ens = fmaxf(en, 1e-8f);
    float fac = fminf(fmaxf(0.9f * powf(ens, -0.2f), 0.2f), 10.0f);
    if (accept) { t = t + hs; cur ^= 1; }
    h = fmaxf(hs * fac, 1e-4f);
  }

  const float* yfin = cur ? g_buf1 : g_buf0;
  head_phase(yfin, wo, bo, out, s_mem, nb);
}

// ---------------- launch: 2 graph nodes total ----------------
extern "C" void kernel_launch(void* const* d_in, const int* in_sizes, int n_in,
                              void* d_out, int out_size) {
  (void)in_sizes; (void)n_in; (void)out_size;
  const float* x  = (const float*)d_in[0];
  const float* w1 = (const float*)d_in[1];
  const float* b1 = (const float*)d_in[2];
  const float* w2 = (const float*)d_in[3];
  const float* b2 = (const float*)d_in[4];
  const float* w3 = (const float*)d_in[5];
  const float* b3 = (const float*)d_in[6];
  const float* wo = (const float*)d_in[7];
  const float* bo = (const float*)d_in[8];

  int dev = 0;
  cudaGetDevice(&dev);
  int nsm = 148;
  cudaDeviceGetAttribute(&nsm, cudaDevAttrMultiProcessorCount, dev);

  const int smem_bytes = 12480 * 4;   // conv2 region is the union max (49920 B)
  cudaFuncSetAttribute(ode_k, cudaFuncAttributeMaxDynamicSharedMemorySize, smem_bytes);

  init_k<<<1, 1>>>();
  ode_k<<<nsm, 256, smem_bytes>>>(x, w1, b1, w2, b2, w3, b3, wo, bo, (float*)d_out);
}

// round 7
// speedup vs baseline: 1.8501x; 1.1767x over previous
#include <cuda_runtime.h>
#include <math.h>

// ---------------- problem dims ----------------
#define PXTOT 32768            // B*H*W = 8*64*64
#define NY    2097152          // PXTOT * 64
#define NH    4194304          // PXTOT * 128
#define NV4   (NY/4)
#define NITERS 32

// ---------------- device state ----------------
__device__ float g_buf0[NY];       // y / ytmp ping-pong
__device__ float g_buf1[NY];
__device__ float g_k[7][NY];
__device__ float g_h1[NH];
__device__ double g_sumsq[NITERS];
__device__ unsigned int g_bar;
__device__ unsigned int g_tk1, g_tk2;

// ---------------- smem layout (floats) for the fused conv2+conv3 phase ------
#define S_IN  0                // [4][66][16]  = 4224
#define S_W2  4224             // [9][16][128] = 18432
#define S_WT  22656            // [9][128]     = 1152
#define S_H2  23808            // [128][136]   = 17408
#define S_W3  41216            // [129][64]    = 8256
#define S_TOT 49472            // * 4 B = 197888 B

// ---------------- f32x2 helpers ----------------
__device__ __forceinline__ unsigned long long pk2(float lo, float hi) {
  unsigned long long r;
  asm("mov.b64 %0, {%1, %2};" : "=l"(r) : "f"(lo), "f"(hi));
  return r;
}
__device__ __forceinline__ unsigned long long dup2(float a) { return pk2(a, a); }
__device__ __forceinline__ unsigned long long fma2(unsigned long long a,
                                                   unsigned long long b,
                                                   unsigned long long c) {
  unsigned long long d;
  asm("fma.rn.f32x2 %0, %1, %2, %3;" : "=l"(d) : "l"(a), "l"(b), "l"(c));
  return d;
}
__device__ __forceinline__ void upk2(float& lo, float& hi, unsigned long long v) {
  asm("mov.b64 {%0, %1}, %2;" : "=f"(lo), "=f"(hi) : "l"(v));
}

// ---------------- init node ----------------
__global__ void init_k() {
  g_bar = 0u; g_tk1 = 0u; g_tk2 = 0u;
  for (int i = 0; i < NITERS; i++) g_sumsq[i] = 0.0;
}

// ---------------- software grid barrier ----------------
__device__ __forceinline__ void gsync(unsigned int& bt, unsigned int nb) {
  __syncthreads();
  if (threadIdx.x == 0) {
    __threadfence();
    atomicAdd(&g_bar, 1u);
    bt += nb;
    while ((int)(*(volatile unsigned int*)&g_bar - bt) < 0) __nanosleep(32);
    __threadfence();
  }
  __syncthreads();
}

// ---------------- dynamic tile tickets ----------------
__device__ __forceinline__ int grab(unsigned int* ctr, unsigned int base, int nt, int* s_t) {
  if (threadIdx.x == 0) {
    unsigned int tk = atomicAdd(ctr, 1u);
    int loc = (int)(tk - base);
    *s_t = (loc < nt) ? loc : -1;
  }
  __syncthreads();
  int r = *s_t;
  __syncthreads();
  return r;
}

// ---------------- conv1: 1x1, (64 + time) -> 128, relu, in -> g_h1 ----------------
// tile = 128 px x 128 f, 256 tiles. smem: in_s[32][132] @0, w_s[32][128] @4224
// Packed f32x2 math (bitwise identical to scalar per-element chains).
__device__ void conv1_phase(const float* __restrict__ in, float tval,
                            const float* __restrict__ w1, const float* __restrict__ b1,
                            float* s, unsigned int& ep, unsigned int nb, int* s_t) {
  float* in_s = s;
  float* w_s  = s + 4224;
  const int tid = threadIdx.x;
  const int f0  = (tid & 15) * 8;
  const int px0 = (tid >> 4) * 8;
  const float4* in4 = (const float4*)in;
  const float4* w14 = (const float4*)w1;
  while (true) {
    int tile = grab(&g_tk1, ep, 256, s_t);
    if (tile < 0) break;
    const int pxbase = tile * 128;
    unsigned long long acc[8][4];     // [px][f-pair]
#pragma unroll
    for (int j = 0; j < 4; j++) {
      unsigned long long bp = pk2(b1[f0+2*j]   + tval * w1[f0+2*j],
                                  b1[f0+2*j+1] + tval * w1[f0+2*j+1]);
#pragma unroll
      for (int i = 0; i < 8; i++) acc[i][j] = bp;
    }
    for (int ch = 0; ch < 64; ch += 32) {
      __syncthreads();
#pragma unroll
      for (int l = 0; l < 4; l++) {
        int idx = tid + l * 256;
        int px = idx >> 3, c4 = idx & 7;
        float4 v = in4[(size_t)(pxbase + px) * 16 + (ch >> 2) + c4];
        in_s[(c4*4+0)*132 + px] = v.x; in_s[(c4*4+1)*132 + px] = v.y;
        in_s[(c4*4+2)*132 + px] = v.z; in_s[(c4*4+3)*132 + px] = v.w;
      }
#pragma unroll
      for (int l = 0; l < 4; l++) {
        int idx = tid + l * 256;
        int k = idx >> 5, f4 = idx & 31;
        ((float4*)w_s)[k * 32 + f4] = w14[(size_t)(1 + ch + k) * 32 + f4];
      }
      __syncthreads();
#pragma unroll 4
      for (int k = 0; k < 32; k++) {
        ulonglong2 wA = *(const ulonglong2*)&w_s[k*128 + f0];
        ulonglong2 wB = *(const ulonglong2*)&w_s[k*128 + f0 + 4];
#pragma unroll
        for (int i = 0; i < 8; i++) {
          unsigned long long a = dup2(in_s[k*132 + px0 + i]);
          acc[i][0] = fma2(a, wA.x, acc[i][0]);
          acc[i][1] = fma2(a, wA.y, acc[i][1]);
          acc[i][2] = fma2(a, wB.x, acc[i][2]);
          acc[i][3] = fma2(a, wB.y, acc[i][3]);
        }
      }
    }
    float4* out4 = (float4*)g_h1;
#pragma unroll
    for (int i = 0; i < 8; i++) {
      float o[8];
      upk2(o[0], o[1], acc[i][0]); upk2(o[2], o[3], acc[i][1]);
      upk2(o[4], o[5], acc[i][2]); upk2(o[6], o[7], acc[i][3]);
#pragma unroll
      for (int j = 0; j < 8; j++) o[j] = fmaxf(o[j], 0.f);
      size_t base = (size_t)(pxbase + px0 + i) * 32 + (f0 >> 2);
      out4[base]     = make_float4(o[0], o[1], o[2], o[3]);
      out4[base + 1] = make_float4(o[4], o[5], o[6], o[7]);
    }
    __syncthreads();
  }
  ep += 256 + nb;
}

// ---------------- fused conv2 + conv3 (+combine / error) ----------------
// tile = 2 output rows (128 px) x 128 f, 256 tiles.
// Stage A: conv2 3x3 SAME (128+t)->128 relu, h2 kept in SMEM.
// Stage B: conv3 1x1 (128+t)->64 on the smem tile; fused dopri5 epilogue.
__device__ void conv23_phase(float tval,
                             const float* __restrict__ w2, const float* __restrict__ b2,
                             const float* __restrict__ w3, const float* __restrict__ b3,
                             int kout, int mode,
                             const float* kl0, const float* kl1,
                             const float* kl2, const float* kl3,
                             float cl0, float cl1, float cl2, float cl3,
                             int nload, float cacc,
                             const float* __restrict__ y, float* __restrict__ yt,
                             float hs, int it,
                             float* s, double* s_red,
                             unsigned int& ep, unsigned int nb, int* s_t) {
  const int tid = threadIdx.x;
  const int f0  = (tid & 15) * 8;       // stage A f range (8)
  const int px0 = (tid >> 4) * 4;       // stage A px-in-row (4)
  const int f0c = (tid & 15) * 4;       // stage B f range (4)
  const int px0c = (tid >> 4) * 8;      // stage B tile-px (8)
  const float4* w24 = (const float4*)w2;
  const float4* w34 = (const float4*)w3;
  const float4* in4 = (const float4*)g_h1;
  const float4* y4  = (const float4*)y;
  float4* yt4 = (float4*)yt;
  const float4* p0 = (const float4*)kl0;
  const float4* p1 = (const float4*)kl1;
  const float4* p2 = (const float4*)kl2;
  const float4* p3 = (const float4*)kl3;
  const unsigned long long td = dup2(tval);
  double local = 0.0;
  while (true) {
    int blk = grab(&g_tk2, ep, 256, s_t);
    if (blk < 0) break;
    const int b   = blk >> 5;
    const int oy0 = (blk & 31) * 2;
    // one-time per tile: w3 to smem (overlaps with conv2 chunks), wt, halo zeros
    for (int l = 0; l < 9; l++) {
      int idx = tid + l * 256;
      if (idx < 2064) ((float4*)(s + S_W3))[idx] = w34[idx];
    }
    for (int idx = tid; idx < 288; idx += 256) {
      int tap = idx >> 5, f4 = idx & 31;
      ((float4*)(s + S_WT))[tap * 32 + f4] = w24[(size_t)tap * 129 * 32 + f4];
    }
    if (tid < 128) {   // zero halo columns (cols 0,65 of 4 rows x 16 ch)
      int r = tid >> 5, rem = tid & 31;
      int col = (rem < 16) ? 0 : 65, c = rem & 15;
      s[S_IN + (r * 66 + col) * 16 + c] = 0.f;
    }
    unsigned long long acc[2][4][4];   // [row][px][f-pair]
    {
      float4 bv0 = ((const float4*)b2)[f0 >> 2];
      float4 bv1 = ((const float4*)b2)[(f0 >> 2) + 1];
      unsigned long long bp0 = pk2(bv0.x, bv0.y), bp1 = pk2(bv0.z, bv0.w);
      unsigned long long bp2 = pk2(bv1.x, bv1.y), bp3 = pk2(bv1.z, bv1.w);
#pragma unroll
      for (int r = 0; r < 2; r++)
#pragma unroll
        for (int i = 0; i < 4; i++) {
          acc[r][i][0] = bp0; acc[r][i][1] = bp1;
          acc[r][i][2] = bp2; acc[r][i][3] = bp3;
        }
    }
    __syncthreads();
    // time-channel contribution with border-valid tap masking
#pragma unroll
    for (int ky = 0; ky < 3; ky++) {
#pragma unroll
      for (int kx = 0; kx < 3; kx++) {
        const float* wb = &s[S_WT + (ky * 3 + kx) * 128 + f0];
        ulonglong2 wA = *(const ulonglong2*)wb;
        ulonglong2 wB = *(const ulonglong2*)(wb + 4);
#pragma unroll
        for (int r = 0; r < 2; r++) {
          int grow = oy0 + r + ky - 1;
          if (grow >= 0 && grow < 64) {
#pragma unroll
            for (int i = 0; i < 4; i++) {
              int col = px0 + i + kx - 1;
              if (col >= 0 && col < 64) {
                acc[r][i][0] = fma2(td, wA.x, acc[r][i][0]);
                acc[r][i][1] = fma2(td, wA.y, acc[r][i][1]);
                acc[r][i][2] = fma2(td, wB.x, acc[r][i][2]);
                acc[r][i][3] = fma2(td, wB.y, acc[r][i][3]);
              }
            }
          }
        }
      }
    }
    // ---- stage A: conv2 over 8 chunks of 16 input channels ----
    for (int ch = 0; ch < 128; ch += 16) {
      __syncthreads();
      // input: 4 rows x 64 px x 16 ch = 1024 float4
#pragma unroll
      for (int l = 0; l < 4; l++) {
        int idx = tid + l * 256;
        int ri = idx >> 8, rem = idx & 255, px = rem >> 2, q = rem & 3;
        int row = oy0 + ri - 1;
        float4 v = make_float4(0.f, 0.f, 0.f, 0.f);
        if (row >= 0 && row < 64)
          v = in4[((size_t)((b * 64 + row) * 64 + px)) * 32 + (ch >> 2) + q];
        *(float4*)&s[S_IN + (ri * 66 + px + 1) * 16 + q * 4] = v;
      }
      // weights: 9 taps x 16 ch x 128 f = 4608 float4
#pragma unroll
      for (int l = 0; l < 18; l++) {
        int idx = tid + l * 256;
        int tap = idx >> 9, rem = idx & 511, cc = rem >> 5, f4 = rem & 31;
        ((float4*)(s + S_W2))[(tap * 16 + cc) * 32 + f4] =
            w24[((size_t)tap * 129 + 1 + ch + cc) * 32 + f4];
      }
      __syncthreads();
      for (int cc = 0; cc < 16; cc++) {
        unsigned long long dv[4][6];
#pragma unroll
        for (int ri = 0; ri < 4; ri++)
#pragma unroll
          for (int d = 0; d < 6; d++)
            dv[ri][d] = dup2(s[S_IN + (ri * 66 + px0 + d) * 16 + cc]);
#pragma unroll
        for (int ky = 0; ky < 3; ky++) {
#pragma unroll
          for (int kx = 0; kx < 3; kx++) {
            const float* wb = &s[S_W2 + ((ky * 3 + kx) * 16 + cc) * 128 + f0];
            ulonglong2 wA = *(const ulonglong2*)wb;
            ulonglong2 wB = *(const ulonglong2*)(wb + 4);
#pragma unroll
            for (int r = 0; r < 2; r++) {
#pragma unroll
              for (int i = 0; i < 4; i++) {
                unsigned long long a = dv[r + ky][i + kx];
                acc[r][i][0] = fma2(a, wA.x, acc[r][i][0]);
                acc[r][i][1] = fma2(a, wA.y, acc[r][i][1]);
                acc[r][i][2] = fma2(a, wB.x, acc[r][i][2]);
                acc[r][i][3] = fma2(a, wB.y, acc[r][i][3]);
              }
            }
          }
        }
      }
    }
    // ---- stage A epilogue: relu + store h2 tile to smem [px][136] ----
#pragma unroll
    for (int r = 0; r < 2; r++) {
#pragma unroll
      for (int i = 0; i < 4; i++) {
        int p_t = r * 64 + px0 + i;
#pragma unroll
        for (int j = 0; j < 4; j++) {
          float lo, hi;
          upk2(lo, hi, acc[r][i][j]);
          *(float2*)&s[S_H2 + p_t * 136 + f0 + 2*j] =
              make_float2(fmaxf(lo, 0.f), fmaxf(hi, 0.f));
        }
      }
    }
    __syncthreads();
    // ---- stage B: conv3 on the smem tile ----
    unsigned long long accB[8][2];
    {
      unsigned long long bpA = pk2(b3[f0c]   + tval * w3[f0c],
                                   b3[f0c+1] + tval * w3[f0c+1]);
      unsigned long long bpB = pk2(b3[f0c+2] + tval * w3[f0c+2],
                                   b3[f0c+3] + tval * w3[f0c+3]);
#pragma unroll
      for (int i = 0; i < 8; i++) { accB[i][0] = bpA; accB[i][1] = bpB; }
    }
#pragma unroll 4
    for (int k = 0; k < 128; k++) {
      ulonglong2 wv = *(const ulonglong2*)&s[S_W3 + (1 + k) * 64 + f0c];
#pragma unroll
      for (int i = 0; i < 8; i++) {
        unsigned long long a = dup2(s[S_H2 + (px0c + i) * 136 + k]);
        accB[i][0] = fma2(a, wv.x, accB[i][0]);
        accB[i][1] = fma2(a, wv.y, accB[i][1]);
      }
    }
    // ---- fused dopri5 epilogue ----
    const size_t pxg0 = (size_t)(b * 64 + oy0) * 64;   // tile px -> global px
    if (mode == 0) {
      float4* out4 = (float4*)&g_k[kout][0];
#pragma unroll
      for (int i = 0; i < 8; i++) {
        size_t off = (pxg0 + px0c + i) * 16 + (f0c >> 2);
        float k0, k1v, k2v, k3v;
        upk2(k0, k1v, accB[i][0]); upk2(k2v, k3v, accB[i][1]);
        float4 kv = make_float4(k0, k1v, k2v, k3v);
        out4[off] = kv;
        float sx = 0.f, sy = 0.f, sz = 0.f, sw = 0.f;
        if (nload > 0) { float4 v = p0[off]; sx = fmaf(cl0,v.x,sx); sy = fmaf(cl0,v.y,sy); sz = fmaf(cl0,v.z,sz); sw = fmaf(cl0,v.w,sw); }
        if (nload > 1) { float4 v = p1[off]; sx = fmaf(cl1,v.x,sx); sy = fmaf(cl1,v.y,sy); sz = fmaf(cl1,v.z,sz); sw = fmaf(cl1,v.w,sw); }
        if (nload > 2) { float4 v = p2[off]; sx = fmaf(cl2,v.x,sx); sy = fmaf(cl2,v.y,sy); sz = fmaf(cl2,v.z,sz); sw = fmaf(cl2,v.w,sw); }
        if (nload > 3) { float4 v = p3[off]; sx = fmaf(cl3,v.x,sx); sy = fmaf(cl3,v.y,sy); sz = fmaf(cl3,v.z,sz); sw = fmaf(cl3,v.w,sw); }
        sx = fmaf(cacc, kv.x, sx); sy = fmaf(cacc, kv.y, sy);
        sz = fmaf(cacc, kv.z, sz); sw = fmaf(cacc, kv.w, sw);
        float4 yv = y4[off];
        yt4[off] = make_float4(fmaf(hs,sx,yv.x), fmaf(hs,sy,yv.y),
                               fmaf(hs,sz,yv.z), fmaf(hs,sw,yv.w));
      }
    } else {
      const float E1f = (float)( 71.0 / 57600.0);
      const float E3f = (float)(-71.0 / 16695.0);
      const float E4f = (float)( 71.0 / 1920.0);
      const float E5f = (float)(-17253.0 / 339200.0);
      const float E6f = (float)( 22.0 / 525.0);
      const float E7f = (float)(-1.0 / 40.0);
      const float4* q1 = (const float4*)g_k[0];
      const float4* q3 = (const float4*)g_k[2];
      const float4* q4 = (const float4*)g_k[3];
      const float4* q5 = (const float4*)g_k[4];
      const float4* q6 = (const float4*)g_k[5];
#pragma unroll
      for (int i = 0; i < 8; i++) {
        size_t off = (pxg0 + px0c + i) * 16 + (f0c >> 2);
        float k0, k1v, k2v, k3v;
        upk2(k0, k1v, accB[i][0]); upk2(k2v, k3v, accB[i][1]);
        float4 v1 = q1[off], v3 = q3[off], v4 = q4[off], v5 = q5[off], v6 = q6[off];
        float4 a = y4[off], bb = yt4[off];   // yt holds y5
#define ECOMP(c, kacc) { \
        float e = hs * (E1f*v1.c + E3f*v3.c + E4f*v4.c + E5f*v5.c + E6f*v6.c + E7f*(kacc)); \
        float sc = 1e-3f + 1e-3f * fmaxf(fabsf(a.c), fabsf(bb.c)); \
        float rr = e / sc; local += (double)rr * (double)rr; }
        ECOMP(x, k0) ECOMP(y, k1v) ECOMP(z, k2v) ECOMP(w, k3v)
#undef ECOMP
      }
    }
    __syncthreads();
  }
  ep += 256 + nb;
  if (mode == 1) {
    __syncthreads();
    s_red[tid] = local;
    __syncthreads();
    for (int o = 128; o > 0; o >>= 1) {
      if (tid < o) s_red[tid] += s_red[tid + o];
      __syncthreads();
    }
    if (tid == 0) atomicAdd(&g_sumsq[it], s_red[0]);
  }
}

// ---------------- output head: 1x1, 64 -> 10 ----------------
__device__ void head_phase(const float* __restrict__ y, const float* __restrict__ wo,
                           const float* __restrict__ bo, float* __restrict__ out,
                           float* s, unsigned int nb) {
  float* w_s = s;        // [64][10]
  float* b_s = s + 640;
  int tid = threadIdx.x;
  __syncthreads();
  for (int i = tid; i < 640; i += 256) w_s[i] = wo[i];
  if (tid < 10) b_s[tid] = bo[tid];
  __syncthreads();
  for (int p = blockIdx.x * 256 + tid; p < PXTOT; p += nb * 256) {
    const float4* yp = (const float4*)(y + (size_t)p * 64);
    float o[10];
#pragma unroll
    for (int k = 0; k < 10; k++) o[k] = b_s[k];
#pragma unroll 4
    for (int c4 = 0; c4 < 16; c4++) {
      float4 v = yp[c4];
      int c = c4 * 4;
#pragma unroll
      for (int k = 0; k < 10; k++)
        o[k] += v.x * w_s[c*10+k] + v.y * w_s[(c+1)*10+k] +
                v.z * w_s[(c+2)*10+k] + v.w * w_s[(c+3)*10+k];
    }
#pragma unroll
    for (int k = 0; k < 10; k++) out[(size_t)p * 10 + k] = o[k];
  }
}

// ---------------- the persistent ODE kernel ----------------
__global__ void __launch_bounds__(256, 1)
ode_k(const float* __restrict__ x,
      const float* __restrict__ w1, const float* __restrict__ b1,
      const float* __restrict__ w2, const float* __restrict__ b2,
      const float* __restrict__ w3, const float* __restrict__ b3,
      const float* __restrict__ wo, const float* __restrict__ bo,
      float* __restrict__ out) {
  extern __shared__ float s_mem[];
  __shared__ double s_red[256];
  __shared__ int s_t;
  const unsigned int nb = gridDim.x;
  unsigned int bt = 0;
  unsigned int e1 = 0, e2 = 0;

  const float A21 = (float)(1.0/5.0);
  const float A31 = (float)(3.0/40.0),  A32 = (float)(9.0/40.0);
  const float A41 = (float)(44.0/45.0), A42 = (float)(-56.0/15.0), A43 = (float)(32.0/9.0);
  const float A51 = (float)(19372.0/6561.0), A52 = (float)(-25360.0/2187.0),
              A53 = (float)(64448.0/6561.0), A54 = (float)(-212.0/729.0);
  const float A61 = (float)(9017.0/3168.0), A62 = (float)(-355.0/33.0),
              A63 = (float)(46732.0/5247.0), A64 = (float)(49.0/176.0),
              A65 = (float)(-5103.0/18656.0);
  const float Bc1 = (float)(35.0/384.0), Bc3 = (float)(500.0/1113.0),
              Bc4 = (float)(125.0/192.0), Bc5 = (float)(-2187.0/6784.0),
              Bc6 = (float)(11.0/84.0);

  // y0 = x
  {
    float4* d = (float4*)g_buf0;
    const float4* sx = (const float4*)x;
    for (int i = blockIdx.x * 256 + threadIdx.x; i < NV4; i += nb * 256) d[i] = sx[i];
  }
  gsync(bt, nb);

  float t = 0.0f, h = 0.1f;
  int cur = 0;

  for (int it = 0; it < NITERS; it++) {
    if (t >= 1.0f) break;       // uniform across all blocks (replicated controller)
    float* y  = cur ? g_buf1 : g_buf0;
    float* yt = cur ? g_buf0 : g_buf1;
    const float hs = fminf(h, 1.0f - t);
    const float t2 = t + hs * 0.2f;
    const float t3 = t + hs * 0.3f;
    const float t4 = t + hs * 0.8f;
    const float t5 = t + hs * (8.0f / 9.0f);
    const float t6 = t + hs;

#define FEVAL(SRC, TV, KO, MODE, P0, P1, P2, P3, C0, C1, C2, C3, NL, CACC)      \
    do {                                                                        \
      conv1_phase((SRC), (TV), w1, b1, s_mem, e1, nb, &s_t); gsync(bt, nb);     \
      conv23_phase((TV), w2, b2, w3, b3, (KO), (MODE), (P0), (P1), (P2), (P3),  \
                   (C0), (C1), (C2), (C3), (NL), (CACC), y, yt, hs, it,         \
                   s_mem, s_red, e2, nb, &s_t);              gsync(bt, nb);     \
    } while (0)

    FEVAL(y,  t,  0, 0, g_k[0], g_k[0], g_k[0], g_k[0], 0,0,0,0,         0, A21);
    FEVAL(yt, t2, 1, 0, g_k[0], g_k[0], g_k[0], g_k[0], A31,0,0,0,       1, A32);
    FEVAL(yt, t3, 2, 0, g_k[0], g_k[1], g_k[0], g_k[0], A41,A42,0,0,     2, A43);
    FEVAL(yt, t4, 3, 0, g_k[0], g_k[1], g_k[2], g_k[0], A51,A52,A53,0,   3, A54);
    FEVAL(yt, t5, 4, 0, g_k[0], g_k[1], g_k[2], g_k[3], A61,A62,A63,A64, 4, A65);
    FEVAL(yt, t6, 5, 0, g_k[0], g_k[2], g_k[3], g_k[4], Bc1,Bc3,Bc4,Bc5, 4, Bc6);  // -> y5
    FEVAL(yt, t6, 6, 1, g_k[0], g_k[0], g_k[0], g_k[0], 0,0,0,0,         0, 0.f); // err
#undef FEVAL

    // replicated controller
    double ss = g_sumsq[it];
    float en = sqrtf((float)(ss / (double)NY));
    int accept = (en <= 1.0f) ? 1 : 0;
    float ens = fmaxf(en, 1e-8f);
    float fac = fminf(fmaxf(0.9f * powf(ens, -0.2f), 0.2f), 10.0f);
    if (accept) { t = t + hs; cur ^= 1; }
    h = fmaxf(hs * fac, 1e-4f);
  }

  const float* yfin = cur ? g_buf1 : g_buf0;
  head_phase(yfin, wo, bo, out, s_mem, nb);
}

// ---------------- launch: 2 graph nodes total ----------------
extern "C" void kernel_launch(void* const* d_in, const int* in_sizes, int n_in,
                              void* d_out, int out_size) {
  (void)in_sizes; (void)n_in; (void)out_size;
  const float* x  = (const float*)d_in[0];
  const float* w1 = (const float*)d_in[1];
  const float* b1 = (const float*)d_in[2];
  const float* w2 = (const float*)d_in[3];
  const float* b2 = (const float*)d_in[4];
  const float* w3 = (const float*)d_in[5];
  const float* b3 = (const float*)d_in[6];
  const float* wo = (const float*)d_in[7];
  const float* bo = (const float*)d_in[8];

  int dev = 0;
  cudaGetDevice(&dev);
  int nsm = 148;
  cudaDeviceGetAttribute(&nsm, cudaDevAttrMultiProcessorCount, dev);

  const int smem_bytes = S_TOT * 4;   // 197888 B
  cudaFuncSetAttribute(ode_k, cudaFuncAttributeMaxDynamicSharedMemorySize, smem_bytes);

  init_k<<<1, 1>>>();
  ode_k<<<nsm, 256, smem_bytes>>>(x, w1, b1, w2, b2, w3, b3, wo, bo, (float*)d_out);
}

// round 9
// speedup vs baseline: 2.0201x; 1.0919x over previous
#include <cuda_runtime.h>
#include <math.h>

// ---------------- problem dims ----------------
#define PXTOT 32768            // B*H*W = 8*64*64
#define NY    2097152          // PXTOT * 64
#define NH    4194304          // PXTOT * 128
#define NV4   (NY/4)
#define NITERS 32

// ---------------- device state ----------------
__device__ float g_buf0[NY];       // y / ytmp ping-pong
__device__ float g_buf1[NY];
__device__ float g_k[7][NY];
__device__ float g_h1[NH];
__device__ double g_sumsq[NITERS];
__device__ unsigned int g_bar;
__device__ unsigned int g_tk1, g_tk2;

// ---------------- smem layout (floats) for the fused conv2+conv3 phase ------
// in_s transposed: [4 ri][16 cc][68 px]  (px contiguous -> vector dv loads)
#define S_IN  0                // 4*16*68      = 4352
#define S_W2  4352             // [9][16][128] = 18432
#define S_WT  22784            // [9][128]     = 1152
#define S_H2  23936            // [128][136]   = 17408
#define S_W3  41344            // [129][64]    = 8256
#define S_TOT 49600            // * 4 B = 198400 B

// ---------------- f32x2 helpers ----------------
__device__ __forceinline__ unsigned long long pk2(float lo, float hi) {
  unsigned long long r;
  asm("mov.b64 %0, {%1, %2};" : "=l"(r) : "f"(lo), "f"(hi));
  return r;
}
__device__ __forceinline__ unsigned long long dup2(float a) { return pk2(a, a); }
__device__ __forceinline__ unsigned long long fma2(unsigned long long a,
                                                   unsigned long long b,
                                                   unsigned long long c) {
  unsigned long long d;
  asm("fma.rn.f32x2 %0, %1, %2, %3;" : "=l"(d) : "l"(a), "l"(b), "l"(c));
  return d;
}
__device__ __forceinline__ void upk2(float& lo, float& hi, unsigned long long v) {
  asm("mov.b64 {%0, %1}, %2;" : "=f"(lo), "=f"(hi) : "l"(v));
}

// ---------------- init node ----------------
__global__ void init_k() {
  g_bar = 0u; g_tk1 = 0u; g_tk2 = 0u;
  for (int i = 0; i < NITERS; i++) g_sumsq[i] = 0.0;
}

// ---------------- software grid barrier ----------------
__device__ __forceinline__ void gsync(unsigned int& bt, unsigned int nb) {
  __syncthreads();
  if (threadIdx.x == 0) {
    __threadfence();
    atomicAdd(&g_bar, 1u);
    bt += nb;
    while ((int)(*(volatile unsigned int*)&g_bar - bt) < 0) __nanosleep(32);
    __threadfence();
  }
  __syncthreads();
}

// ---------------- dynamic tile tickets ----------------
__device__ __forceinline__ int grab(unsigned int* ctr, unsigned int base, int nt, int* s_t) {
  if (threadIdx.x == 0) {
    unsigned int tk = atomicAdd(ctr, 1u);
    int loc = (int)(tk - base);
    *s_t = (loc < nt) ? loc : -1;
  }
  __syncthreads();
  int r = *s_t;
  __syncthreads();
  return r;
}

// ---------------- conv1: 1x1, (64 + time) -> 128, relu, in -> g_h1 ----------------
// tile = 128 px x 128 f, 256 tiles. smem: in_s[32][132] @0, w_s[32][128] @4224
__device__ void conv1_phase(const float* __restrict__ in, float tval,
                            const float* __restrict__ w1, const float* __restrict__ b1,
                            float* s, unsigned int& ep, unsigned int nb, int* s_t) {
  float* in_s = s;
  float* w_s  = s + 4224;
  const int tid = threadIdx.x;
  const int f0  = (tid & 15) * 8;
  const int px0 = (tid >> 4) * 8;
  const float4* in4 = (const float4*)in;
  const float4* w14 = (const float4*)w1;
  while (true) {
    int tile = grab(&g_tk1, ep, 256, s_t);
    if (tile < 0) break;
    const int pxbase = tile * 128;
    unsigned long long acc[8][4];     // [px][f-pair]
#pragma unroll
    for (int j = 0; j < 4; j++) {
      unsigned long long bp = pk2(b1[f0+2*j]   + tval * w1[f0+2*j],
                                  b1[f0+2*j+1] + tval * w1[f0+2*j+1]);
#pragma unroll
      for (int i = 0; i < 8; i++) acc[i][j] = bp;
    }
    for (int ch = 0; ch < 64; ch += 32) {
      __syncthreads();
#pragma unroll
      for (int l = 0; l < 4; l++) {
        int idx = tid + l * 256;
        int px = idx >> 3, c4 = idx & 7;
        float4 v = in4[(size_t)(pxbase + px) * 16 + (ch >> 2) + c4];
        in_s[(c4*4+0)*132 + px] = v.x; in_s[(c4*4+1)*132 + px] = v.y;
        in_s[(c4*4+2)*132 + px] = v.z; in_s[(c4*4+3)*132 + px] = v.w;
      }
#pragma unroll
      for (int l = 0; l < 4; l++) {
        int idx = tid + l * 256;
        int k = idx >> 5, f4 = idx & 31;
        ((float4*)w_s)[k * 32 + f4] = w14[(size_t)(1 + ch + k) * 32 + f4];
      }
      __syncthreads();
#pragma unroll 4
      for (int k = 0; k < 32; k++) {
        ulonglong2 wA = *(const ulonglong2*)&w_s[k*128 + f0];
        ulonglong2 wB = *(const ulonglong2*)&w_s[k*128 + f0 + 4];
        float4 a0 = *(const float4*)&in_s[k*132 + px0];
        float4 a1 = *(const float4*)&in_s[k*132 + px0 + 4];
        const float* ap = (const float*)&a0;
#pragma unroll
        for (int i = 0; i < 4; i++) {
          unsigned long long a = dup2(ap[i]);
          acc[i][0] = fma2(a, wA.x, acc[i][0]);
          acc[i][1] = fma2(a, wA.y, acc[i][1]);
          acc[i][2] = fma2(a, wB.x, acc[i][2]);
          acc[i][3] = fma2(a, wB.y, acc[i][3]);
        }
        const float* ap1 = (const float*)&a1;
#pragma unroll
        for (int i = 0; i < 4; i++) {
          unsigned long long a = dup2(ap1[i]);
          acc[4+i][0] = fma2(a, wA.x, acc[4+i][0]);
          acc[4+i][1] = fma2(a, wA.y, acc[4+i][1]);
          acc[4+i][2] = fma2(a, wB.x, acc[4+i][2]);
          acc[4+i][3] = fma2(a, wB.y, acc[4+i][3]);
        }
      }
    }
    float4* out4 = (float4*)g_h1;
#pragma unroll
    for (int i = 0; i < 8; i++) {
      float o[8];
      upk2(o[0], o[1], acc[i][0]); upk2(o[2], o[3], acc[i][1]);
      upk2(o[4], o[5], acc[i][2]); upk2(o[6], o[7], acc[i][3]);
#pragma unroll
      for (int j = 0; j < 8; j++) o[j] = fmaxf(o[j], 0.f);
      size_t base = (size_t)(pxbase + px0 + i) * 32 + (f0 >> 2);
      out4[base]     = make_float4(o[0], o[1], o[2], o[3]);
      out4[base + 1] = make_float4(o[4], o[5], o[6], o[7]);
    }
    __syncthreads();
  }
  ep += 256 + nb;
}

// ---------------- fused conv2 + conv3 (+combine / error) ----------------
// tile = 2 output rows (128 px) x 128 f, 256 tiles.
__device__ void conv23_phase(float tval,
                             const float* __restrict__ w2, const float* __restrict__ b2,
                             const float* __restrict__ w3, const float* __restrict__ b3,
                             int kout, int mode,
                             const float* kl0, const float* kl1,
                             const float* kl2, const float* kl3,
                             float cl0, float cl1, float cl2, float cl3,
                             int nload, float cacc,
                             const float* __restrict__ y, float* __restrict__ yt,
                             float hs, int it,
                             float* s, double* s_red,
                             unsigned int& ep, unsigned int nb, int* s_t) {
  const int tid = threadIdx.x;
  const int f0  = (tid & 15) * 8;       // stage A f range (8)
  const int px0 = (tid >> 4) * 4;       // stage A px-in-row (4)
  const int f0c = (tid & 15) * 4;       // stage B f range (4)
  const int px0c = (tid >> 4) * 8;      // stage B tile-px (8)
  const float4* w24 = (const float4*)w2;
  const float4* w34 = (const float4*)w3;
  const float4* in4 = (const float4*)g_h1;
  const float4* y4  = (const float4*)y;
  float4* yt4 = (float4*)yt;
  const float4* p0 = (const float4*)kl0;
  const float4* p1 = (const float4*)kl1;
  const float4* p2 = (const float4*)kl2;
  const float4* p3 = (const float4*)kl3;
  const unsigned long long td = dup2(tval);
  double local = 0.0;
  while (true) {
    int blk = grab(&g_tk2, ep, 256, s_t);
    if (blk < 0) break;
    const int b   = blk >> 5;
    const int oy0 = (blk & 31) * 2;
    // one-time per tile: w3, wt, halo zeros
    for (int l = 0; l < 9; l++) {
      int idx = tid + l * 256;
      if (idx < 2064) ((float4*)(s + S_W3))[idx] = w34[idx];
    }
    for (int idx = tid; idx < 288; idx += 256) {
      int tap = idx >> 5, f4 = idx & 31;
      ((float4*)(s + S_WT))[tap * 32 + f4] = w24[(size_t)tap * 129 * 32 + f4];
    }
    if (tid < 128) {   // zero halo px columns 0,65 for all (ri, cc)
      int ri = tid >> 5, cc = (tid >> 1) & 15, col = (tid & 1) * 65;
      s[S_IN + (ri * 16 + cc) * 68 + col] = 0.f;
    }
    unsigned long long acc[2][4][4];   // [row][px][f-pair]
    {
      float4 bv0 = ((const float4*)b2)[f0 >> 2];
      float4 bv1 = ((const float4*)b2)[(f0 >> 2) + 1];
      unsigned long long bp0 = pk2(bv0.x, bv0.y), bp1 = pk2(bv0.z, bv0.w);
      unsigned long long bp2 = pk2(bv1.x, bv1.y), bp3 = pk2(bv1.z, bv1.w);
#pragma unroll
      for (int r = 0; r < 2; r++)
#pragma unroll
        for (int i = 0; i < 4; i++) {
          acc[r][i][0] = bp0; acc[r][i][1] = bp1;
          acc[r][i][2] = bp2; acc[r][i][3] = bp3;
        }
    }
    __syncthreads();
    // time-channel contribution with border-valid tap masking
#pragma unroll
    for (int ky = 0; ky < 3; ky++) {
#pragma unroll
      for (int kx = 0; kx < 3; kx++) {
        const float* wb = &s[S_WT + (ky * 3 + kx) * 128 + f0];
        ulonglong2 wA = *(const ulonglong2*)wb;
        ulonglong2 wB = *(const ulonglong2*)(wb + 4);
#pragma unroll
        for (int r = 0; r < 2; r++) {
          int grow = oy0 + r + ky - 1;
          if (grow >= 0 && grow < 64) {
#pragma unroll
            for (int i = 0; i < 4; i++) {
              int col = px0 + i + kx - 1;
              if (col >= 0 && col < 64) {
                acc[r][i][0] = fma2(td, wA.x, acc[r][i][0]);
                acc[r][i][1] = fma2(td, wA.y, acc[r][i][1]);
                acc[r][i][2] = fma2(td, wB.x, acc[r][i][2]);
                acc[r][i][3] = fma2(td, wB.y, acc[r][i][3]);
              }
            }
          }
        }
      }
    }
    // ---- stage A: conv2 over 8 chunks of 16 input channels ----
    for (int ch = 0; ch < 128; ch += 16) {
      __syncthreads();
      // input: 4 rows x 64 px x 16 ch; store transposed [ri][cc][68 px]
#pragma unroll
      for (int l = 0; l < 4; l++) {
        int idx = tid + l * 256;          // ri == l
        int px = (idx & 255) >> 2, q = idx & 3;
        int row = oy0 + l - 1;
        float4 v = make_float4(0.f, 0.f, 0.f, 0.f);
        if (row >= 0 && row < 64)
          v = in4[((size_t)((b * 64 + row) * 64 + px)) * 32 + (ch >> 2) + q];
        float* bp = &s[S_IN + (l * 16 + q * 4) * 68 + px + 1];
        bp[0] = v.x; bp[68] = v.y; bp[136] = v.z; bp[204] = v.w;
      }
      // weights: 9 taps x 16 ch x 128 f = 4608 float4
#pragma unroll
      for (int l = 0; l < 18; l++) {
        int idx = tid + l * 256;
        int tap = idx >> 9, rem = idx & 511, cc = rem >> 5, f4 = rem & 31;
        ((float4*)(s + S_W2))[(tap * 16 + cc) * 32 + f4] =
            w24[((size_t)tap * 129 + 1 + ch + cc) * 32 + f4];
      }
      __syncthreads();
      for (int cc = 0; cc < 16; cc++) {
        unsigned long long dv[4][6];
#pragma unroll
        for (int ri = 0; ri < 4; ri++) {
          const float* bp = &s[S_IN + (ri * 16 + cc) * 68 + px0];
          float4 a = *(const float4*)bp;
          float2 t2 = *(const float2*)(bp + 4);
          dv[ri][0] = dup2(a.x); dv[ri][1] = dup2(a.y);
          dv[ri][2] = dup2(a.z); dv[ri][3] = dup2(a.w);
          dv[ri][4] = dup2(t2.x); dv[ri][5] = dup2(t2.y);
        }
#pragma unroll
        for (int ky = 0; ky < 3; ky++) {
#pragma unroll
          for (int kx = 0; kx < 3; kx++) {
            const float* wb = &s[S_W2 + ((ky * 3 + kx) * 16 + cc) * 128 + f0];
            ulonglong2 wA = *(const ulonglong2*)wb;
            ulonglong2 wB = *(const ulonglong2*)(wb + 4);
#pragma unroll
            for (int r = 0; r < 2; r++) {
#pragma unroll
              for (int i = 0; i < 4; i++) {
                unsigned long long a = dv[r + ky][i + kx];
                acc[r][i][0] = fma2(a, wA.x, acc[r][i][0]);
                acc[r][i][1] = fma2(a, wA.y, acc[r][i][1]);
                acc[r][i][2] = fma2(a, wB.x, acc[r][i][2]);
                acc[r][i][3] = fma2(a, wB.y, acc[r][i][3]);
              }
            }
          }
        }
      }
    }
    // ---- stage A epilogue: relu + store h2 tile to smem [px][136] ----
#pragma unroll
    for (int r = 0; r < 2; r++) {
#pragma unroll
      for (int i = 0; i < 4; i++) {
        int p_t = r * 64 + px0 + i;
#pragma unroll
        for (int j = 0; j < 4; j++) {
          float lo, hi;
          upk2(lo, hi, acc[r][i][j]);
          *(float2*)&s[S_H2 + p_t * 136 + f0 + 2*j] =
              make_float2(fmaxf(lo, 0.f), fmaxf(hi, 0.f));
        }
      }
    }
    __syncthreads();
    // ---- stage B: conv3 on the smem tile (k blocked by 4, vector a loads) ----
    unsigned long long accB[8][2];
    {
      unsigned long long bpA = pk2(b3[f0c]   + tval * w3[f0c],
                                   b3[f0c+1] + tval * w3[f0c+1]);
      unsigned long long bpB = pk2(b3[f0c+2] + tval * w3[f0c+2],
                                   b3[f0c+3] + tval * w3[f0c+3]);
#pragma unroll
      for (int i = 0; i < 8; i++) { accB[i][0] = bpA; accB[i][1] = bpB; }
    }
#pragma unroll 2
    for (int k0 = 0; k0 < 128; k0 += 4) {
      float4 av[8];
#pragma unroll
      for (int i = 0; i < 8; i++)
        av[i] = *(const float4*)&s[S_H2 + (px0c + i) * 136 + k0];
#pragma unroll
      for (int kk = 0; kk < 4; kk++) {
        ulonglong2 wv = *(const ulonglong2*)&s[S_W3 + (1 + k0 + kk) * 64 + f0c];
#pragma unroll
        for (int i = 0; i < 8; i++) {
          unsigned long long a = dup2(((const float*)&av[i])[kk]);
          accB[i][0] = fma2(a, wv.x, accB[i][0]);
          accB[i][1] = fma2(a, wv.y, accB[i][1]);
        }
      }
    }
    // ---- fused dopri5 epilogue ----
    const size_t pxg0 = (size_t)(b * 64 + oy0) * 64;   // tile px -> global px
    if (mode == 0) {
      float4* out4 = (float4*)&g_k[kout][0];
#pragma unroll
      for (int i = 0; i < 8; i++) {
        size_t off = (pxg0 + px0c + i) * 16 + (f0c >> 2);
        float k0v, k1v, k2v, k3v;
        upk2(k0v, k1v, accB[i][0]); upk2(k2v, k3v, accB[i][1]);
        float4 kv = make_float4(k0v, k1v, k2v, k3v);
        out4[off] = kv;
        float sx = 0.f, sy = 0.f, sz = 0.f, sw = 0.f;
        if (nload > 0) { float4 v = p0[off]; sx = fmaf(cl0,v.x,sx); sy = fmaf(cl0,v.y,sy); sz = fmaf(cl0,v.z,sz); sw = fmaf(cl0,v.w,sw); }
        if (nload > 1) { float4 v = p1[off]; sx = fmaf(cl1,v.x,sx); sy = fmaf(cl1,v.y,sy); sz = fmaf(cl1,v.z,sz); sw = fmaf(cl1,v.w,sw); }
        if (nload > 2) { float4 v = p2[off]; sx = fmaf(cl2,v.x,sx); sy = fmaf(cl2,v.y,sy); sz = fmaf(cl2,v.z,sz); sw = fmaf(cl2,v.w,sw); }
        if (nload > 3) { float4 v = p3[off]; sx = fmaf(cl3,v.x,sx); sy = fmaf(cl3,v.y,sy); sz = fmaf(cl3,v.z,sz); sw = fmaf(cl3,v.w,sw); }
        sx = fmaf(cacc, kv.x, sx); sy = fmaf(cacc, kv.y, sy);
        sz = fmaf(cacc, kv.z, sz); sw = fmaf(cacc, kv.w, sw);
        float4 yv = y4[off];
        yt4[off] = make_float4(fmaf(hs,sx,yv.x), fmaf(hs,sy,yv.y),
                               fmaf(hs,sz,yv.z), fmaf(hs,sw,yv.w));
      }
    } else {
      const float E1f = (float)( 71.0 / 57600.0);
      const float E3f = (float)(-71.0 / 16695.0);
      const float E4f = (float)( 71.0 / 1920.0);
      const float E5f = (float)(-17253.0 / 339200.0);
      const float E6f = (float)( 22.0 / 525.0);
      const float E7f = (float)(-1.0 / 40.0);
      const float4* q1 = (const float4*)g_k[0];
      const float4* q3 = (const float4*)g_k[2];
      const float4* q4 = (const float4*)g_k[3];
      const float4* q5 = (const float4*)g_k[4];
      const float4* q6 = (const float4*)g_k[5];
#pragma unroll
      for (int i = 0; i < 8; i++) {
        size_t off = (pxg0 + px0c + i) * 16 + (f0c >> 2);
        float k0v, k1v, k2v, k3v;
        upk2(k0v, k1v, accB[i][0]); upk2(k2v, k3v, accB[i][1]);
        float4 v1 = q1[off], v3 = q3[off], v4 = q4[off], v5 = q5[off], v6 = q6[off];
        float4 a = y4[off], bb = yt4[off];   // yt holds y5
#define ECOMP(c, kacc) { \
        float e = hs * (E1f*v1.c + E3f*v3.c + E4f*v4.c + E5f*v5.c + E6f*v6.c + E7f*(kacc)); \
        float sc = 1e-3f + 1e-3f * fmaxf(fabsf(a.c), fabsf(bb.c)); \
        float rr = e / sc; local += (double)rr * (double)rr; }
        ECOMP(x, k0v) ECOMP(y, k1v) ECOMP(z, k2v) ECOMP(w, k3v)
#undef ECOMP
      }
    }
    __syncthreads();
  }
  ep += 256 + nb;
  if (mode == 1) {
    __syncthreads();
    s_red[tid] = local;
    __syncthreads();
    for (int o = 128; o > 0; o >>= 1) {
      if (tid < o) s_red[tid] += s_red[tid + o];
      __syncthreads();
    }
    if (tid == 0) atomicAdd(&g_sumsq[it], s_red[0]);
  }
}

// ---------------- output head: 1x1, 64 -> 10 ----------------
__device__ void head_phase(const float* __restrict__ y, const float* __restrict__ wo,
                           const float* __restrict__ bo, float* __restrict__ out,
                           float* s, unsigned int nb) {
  float* w_s = s;        // [64][10]
  float* b_s = s + 640;
  int tid = threadIdx.x;
  __syncthreads();
  for (int i = tid; i < 640; i += 256) w_s[i] = wo[i];
  if (tid < 10) b_s[tid] = bo[tid];
  __syncthreads();
  for (int p = blockIdx.x * 256 + tid; p < PXTOT; p += nb * 256) {
    const float4* yp = (const float4*)(y + (size_t)p * 64);
    float o[10];
#pragma unroll
    for (int k = 0; k < 10; k++) o[k] = b_s[k];
#pragma unroll 4
    for (int c4 = 0; c4 < 16; c4++) {
      float4 v = yp[c4];
      int c = c4 * 4;
#pragma unroll
      for (int k = 0; k < 10; k++)
        o[k] += v.x * w_s[c*10+k] + v.y * w_s[(c+1)*10+k] +
                v.z * w_s[(c+2)*10+k] + v.w * w_s[(c+3)*10+k];
    }
#pragma unroll
    for (int k = 0; k < 10; k++) out[(size_t)p * 10 + k] = o[k];
  }
}

// ---------------- the persistent ODE kernel ----------------
__global__ void __launch_bounds__(256, 1)
ode_k(const float* __restrict__ x,
      const float* __restrict__ w1, const float* __restrict__ b1,
      const float* __restrict__ w2, const float* __restrict__ b2,
      const float* __restrict__ w3, const float* __restrict__ b3,
      const float* __restrict__ wo, const float* __restrict__ bo,
      float* __restrict__ out) {
  extern __shared__ float s_mem[];
  __shared__ double s_red[256];
  __shared__ int s_t;
  const unsigned int nb = gridDim.x;
  unsigned int bt = 0;
  unsigned int e1 = 0, e2 = 0;

  const float A21 = (float)(1.0/5.0);
  const float A31 = (float)(3.0/40.0),  A32 = (float)(9.0/40.0);
  const float A41 = (float)(44.0/45.0), A42 = (float)(-56.0/15.0), A43 = (float)(32.0/9.0);
  const float A51 = (float)(19372.0/6561.0), A52 = (float)(-25360.0/2187.0),
              A53 = (float)(64448.0/6561.0), A54 = (float)(-212.0/729.0);
  const float A61 = (float)(9017.0/3168.0), A62 = (float)(-355.0/33.0),
              A63 = (float)(46732.0/5247.0), A64 = (float)(49.0/176.0),
              A65 = (float)(-5103.0/18656.0);
  const float Bc1 = (float)(35.0/384.0), Bc3 = (float)(500.0/1113.0),
              Bc4 = (float)(125.0/192.0), Bc5 = (float)(-2187.0/6784.0),
              Bc6 = (float)(11.0/84.0);

  // y0 = x
  {
    float4* d = (float4*)g_buf0;
    const float4* sx = (const float4*)x;
    for (int i = blockIdx.x * 256 + threadIdx.x; i < NV4; i += nb * 256) d[i] = sx[i];
  }
  gsync(bt, nb);

  float t = 0.0f, h = 0.1f;
  int cur = 0;

  for (int it = 0; it < NITERS; it++) {
    if (t >= 1.0f) break;       // uniform across all blocks (replicated controller)
    float* y  = cur ? g_buf1 : g_buf0;
    float* yt = cur ? g_buf0 : g_buf1;
    const float hs = fminf(h, 1.0f - t);
    const float t2 = t + hs * 0.2f;
    const float t3 = t + hs * 0.3f;
    const float t4 = t + hs * 0.8f;
    const float t5 = t + hs * (8.0f / 9.0f);
    const float t6 = t + hs;

#define FEVAL(SRC, TV, KO, MODE, P0, P1, P2, P3, C0, C1, C2, C3, NL, CACC)      \
    do {                                                                        \
      conv1_phase((SRC), (TV), w1, b1, s_mem, e1, nb, &s_t); gsync(bt, nb);     \
      conv23_phase((TV), w2, b2, w3, b3, (KO), (MODE), (P0), (P1), (P2), (P3),  \
                   (C0), (C1), (C2), (C3), (NL), (CACC), y, yt, hs, it,         \
                   s_mem, s_red, e2, nb, &s_t);              gsync(bt, nb);     \
    } while (0)

    FEVAL(y,  t,  0, 0, g_k[0], g_k[0], g_k[0], g_k[0], 0,0,0,0,         0, A21);
    FEVAL(yt, t2, 1, 0, g_k[0], g_k[0], g_k[0], g_k[0], A31,0,0,0,       1, A32);
    FEVAL(yt, t3, 2, 0, g_k[0], g_k[1], g_k[0], g_k[0], A41,A42,0,0,     2, A43);
    FEVAL(yt, t4, 3, 0, g_k[0], g_k[1], g_k[2], g_k[0], A51,A52,A53,0,   3, A54);
    FEVAL(yt, t5, 4, 0, g_k[0], g_k[1], g_k[2], g_k[3], A61,A62,A63,A64, 4, A65);
    FEVAL(yt, t6, 5, 0, g_k[0], g_k[2], g_k[3], g_k[4], Bc1,Bc3,Bc4,Bc5, 4, Bc6);  // -> y5
    FEVAL(yt, t6, 6, 1, g_k[0], g_k[0], g_k[0], g_k[0], 0,0,0,0,         0, 0.f); // err
#undef FEVAL

    // replicated controller
    double ss = g_sumsq[it];
    float en = sqrtf((float)(ss / (double)NY));
    int accept = (en <= 1.0f) ? 1 : 0;
    float ens = fmaxf(en, 1e-8f);
    float fac = fminf(fmaxf(0.9f * powf(ens, -0.2f), 0.2f), 10.0f);
    if (accept) { t = t + hs; cur ^= 1; }
    h = fmaxf(hs * fac, 1e-4f);
  }

  const float* yfin = cur ? g_buf1 : g_buf0;
  head_phase(yfin, wo, bo, out, s_mem, nb);
}

// ---------------- launch: 2 graph nodes total ----------------
extern "C" void kernel_launch(void* const* d_in, const int* in_sizes, int n_in,
                              void* d_out, int out_size) {
  (void)in_sizes; (void)n_in; (void)out_size;
  const float* x  = (const float*)d_in[0];
  const float* w1 = (const float*)d_in[1];
  const float* b1 = (const float*)d_in[2];
  const float* w2 = (const float*)d_in[3];
  const float* b2 = (const float*)d_in[4];
  const float* w3 = (const float*)d_in[5];
  const float* b3 = (const float*)d_in[6];
  const float* wo = (const float*)d_in[7];
  const float* bo = (const float*)d_in[8];

  int dev = 0;
  cudaGetDevice(&dev);
  int nsm = 148;
  cudaDeviceGetAttribute(&nsm, cudaDevAttrMultiProcessorCount, dev);

  const int smem_bytes = S_TOT * 4;   // 198400 B
  cudaFuncSetAttribute(ode_k, cudaFuncAttributeMaxDynamicSharedMemorySize, smem_bytes);

  init_k<<<1, 1>>>();
  ode_k<<<nsm, 256, smem_bytes>>>(x, w1, b1, w2, b2, w3, b3, wo, bo, (float*)d_out);
}

// round 10
// speedup vs baseline: 2.3004x; 1.1388x over previous
#include <cuda_runtime.h>
#include <math.h>

// ---------------- problem dims ----------------
#define PXTOT 32768            // B*H*W = 8*64*64
#define NY    2097152          // PXTOT * 64
#define NH    4194304          // PXTOT * 128
#define NV4   (NY/4)
#define NITERS 32
#define NTHR  512

// ---------------- device state ----------------
__device__ float g_buf0[NY];       // y / ytmp ping-pong
__device__ float g_buf1[NY];
__device__ float g_k[7][NY];
__device__ float g_h1[NH];
__device__ double g_sumsq[NITERS];
__device__ unsigned int g_bar;
__device__ unsigned int g_tk1, g_tk2;

// ---------------- smem layout (floats) for the fused conv2+conv3 phase ------
// in_s transposed: [4 ri][16 cc][68 px]  (px contiguous -> vector dv loads)
#define S_IN  0                // 4*16*68      = 4352
#define S_W2  4352             // [9][16][128] = 18432
#define S_WT  22784            // [9][128]     = 1152
#define S_H2  23936            // [128][136]   = 17408
#define S_W3  41344            // [129][64]    = 8256
#define S_TOT 49600            // * 4 B = 198400 B

// ---------------- f32x2 helpers ----------------
__device__ __forceinline__ unsigned long long pk2(float lo, float hi) {
  unsigned long long r;
  asm("mov.b64 %0, {%1, %2};" : "=l"(r) : "f"(lo), "f"(hi));
  return r;
}
__device__ __forceinline__ unsigned long long dup2(float a) { return pk2(a, a); }
__device__ __forceinline__ unsigned long long fma2(unsigned long long a,
                                                   unsigned long long b,
                                                   unsigned long long c) {
  unsigned long long d;
  asm("fma.rn.f32x2 %0, %1, %2, %3;" : "=l"(d) : "l"(a), "l"(b), "l"(c));
  return d;
}
__device__ __forceinline__ void upk2(float& lo, float& hi, unsigned long long v) {
  asm("mov.b64 {%0, %1}, %2;" : "=f"(lo), "=f"(hi) : "l"(v));
}

// ---------------- init node ----------------
__global__ void init_k() {
  g_bar = 0u; g_tk1 = 0u; g_tk2 = 0u;
  for (int i = 0; i < NITERS; i++) g_sumsq[i] = 0.0;
}

// ---------------- software grid barrier ----------------
__device__ __forceinline__ void gsync(unsigned int& bt, unsigned int nb) {
  __syncthreads();
  if (threadIdx.x == 0) {
    __threadfence();
    atomicAdd(&g_bar, 1u);
    bt += nb;
    while ((int)(*(volatile unsigned int*)&g_bar - bt) < 0) __nanosleep(32);
    __threadfence();
  }
  __syncthreads();
}

// ---------------- dynamic tile tickets ----------------
__device__ __forceinline__ int grab(unsigned int* ctr, unsigned int base, int nt, int* s_t) {
  if (threadIdx.x == 0) {
    unsigned int tk = atomicAdd(ctr, 1u);
    int loc = (int)(tk - base);
    *s_t = (loc < nt) ? loc : -1;
  }
  __syncthreads();
  int r = *s_t;
  __syncthreads();
  return r;
}

// ---------------- conv1: 1x1, (64 + time) -> 128, relu, in -> g_h1 ----------------
// tile = 128 px x 128 f, 256 tiles. thread tile: 8 px x 4 f.
__device__ void conv1_phase(const float* __restrict__ in, float tval,
                            const float* __restrict__ w1, const float* __restrict__ b1,
                            float* s, unsigned int& ep, unsigned int nb, int* s_t) {
  float* in_s = s;                 // [32 ch][132 px]
  float* w_s  = s + 4224;          // [32 ch][128 f]
  const int tid = threadIdx.x;
  const int f0  = (tid & 31) * 4;
  const int px0 = (tid >> 5) * 8;
  const float4* in4 = (const float4*)in;
  const float4* w14 = (const float4*)w1;
  while (true) {
    int tile = grab(&g_tk1, ep, 256, s_t);
    if (tile < 0) break;
    const int pxbase = tile * 128;
    unsigned long long acc[8][2];     // [px][f-pair]
    {
      unsigned long long bp0 = pk2(b1[f0]   + tval * w1[f0],
                                   b1[f0+1] + tval * w1[f0+1]);
      unsigned long long bp1 = pk2(b1[f0+2] + tval * w1[f0+2],
                                   b1[f0+3] + tval * w1[f0+3]);
#pragma unroll
      for (int i = 0; i < 8; i++) { acc[i][0] = bp0; acc[i][1] = bp1; }
    }
    for (int ch = 0; ch < 64; ch += 32) {
      __syncthreads();
#pragma unroll
      for (int l = 0; l < 2; l++) {
        int idx = tid + l * NTHR;
        int px = idx >> 3, c4 = idx & 7;
        float4 v = in4[(size_t)(pxbase + px) * 16 + (ch >> 2) + c4];
        in_s[(c4*4+0)*132 + px] = v.x; in_s[(c4*4+1)*132 + px] = v.y;
        in_s[(c4*4+2)*132 + px] = v.z; in_s[(c4*4+3)*132 + px] = v.w;
      }
#pragma unroll
      for (int l = 0; l < 2; l++) {
        int idx = tid + l * NTHR;
        int k = idx >> 5, f4 = idx & 31;
        ((float4*)w_s)[k * 32 + f4] = w14[(size_t)(1 + ch + k) * 32 + f4];
      }
      __syncthreads();
#pragma unroll 4
      for (int k = 0; k < 32; k++) {
        ulonglong2 wA = *(const ulonglong2*)&w_s[k*128 + f0];
        float4 a0 = *(const float4*)&in_s[k*132 + px0];
        float4 a1 = *(const float4*)&in_s[k*132 + px0 + 4];
        const float* ap = (const float*)&a0;
#pragma unroll
        for (int i = 0; i < 4; i++) {
          unsigned long long a = dup2(ap[i]);
          acc[i][0] = fma2(a, wA.x, acc[i][0]);
          acc[i][1] = fma2(a, wA.y, acc[i][1]);
        }
        const float* ap1 = (const float*)&a1;
#pragma unroll
        for (int i = 0; i < 4; i++) {
          unsigned long long a = dup2(ap1[i]);
          acc[4+i][0] = fma2(a, wA.x, acc[4+i][0]);
          acc[4+i][1] = fma2(a, wA.y, acc[4+i][1]);
        }
      }
    }
    float4* out4 = (float4*)g_h1;
#pragma unroll
    for (int i = 0; i < 8; i++) {
      float o[4];
      upk2(o[0], o[1], acc[i][0]); upk2(o[2], o[3], acc[i][1]);
#pragma unroll
      for (int j = 0; j < 4; j++) o[j] = fmaxf(o[j], 0.f);
      out4[(size_t)(pxbase + px0 + i) * 32 + (f0 >> 2)] =
          make_float4(o[0], o[1], o[2], o[3]);
    }
    __syncthreads();
  }
  ep += 256 + nb;
}

// ---------------- fused conv2 + conv3 (+combine / error) ----------------
// tile = 2 output rows (128 px) x 128 f, 256 tiles.
// stage A thread tile: 2 rows x 4 px x 4 f; stage B: 8 px x 2 f.
__device__ void conv23_phase(float tval,
                             const float* __restrict__ w2, const float* __restrict__ b2,
                             const float* __restrict__ w3, const float* __restrict__ b3,
                             int kout, int mode,
                             const float* kl0, const float* kl1,
                             const float* kl2, const float* kl3,
                             float cl0, float cl1, float cl2, float cl3,
                             int nload, float cacc,
                             const float* __restrict__ y, float* __restrict__ yt,
                             float hs, int it,
                             float* s, double* s_red,
                             unsigned int& ep, unsigned int nb, int* s_t) {
  const int tid = threadIdx.x;
  const int f0   = (tid & 31) * 4;      // stage A f range (4)
  const int px0  = (tid >> 5) * 4;      // stage A px-in-row (4)
  const int f0c  = (tid & 31) * 2;      // stage B f range (2)
  const int px0c = (tid >> 5) * 8;      // stage B tile-px (8)
  const float4* w24 = (const float4*)w2;
  const float4* w34 = (const float4*)w3;
  const float4* in4 = (const float4*)g_h1;
  const float2* y2  = (const float2*)y;
  float2* yt2 = (float2*)yt;
  const float2* p0 = (const float2*)kl0;
  const float2* p1 = (const float2*)kl1;
  const float2* p2 = (const float2*)kl2;
  const float2* p3 = (const float2*)kl3;
  const unsigned long long td = dup2(tval);
  double local = 0.0;
  while (true) {
    int blk = grab(&g_tk2, ep, 256, s_t);
    if (blk < 0) break;
    const int b   = blk >> 5;
    const int oy0 = (blk & 31) * 2;
    // one-time per tile: w3, wt, halo zeros
#pragma unroll
    for (int l = 0; l < 5; l++) {
      int idx = tid + l * NTHR;
      if (idx < 2064) ((float4*)(s + S_W3))[idx] = w34[idx];
    }
    if (tid < 288) {
      int tap = tid >> 5, f4 = tid & 31;
      ((float4*)(s + S_WT))[tap * 32 + f4] = w24[(size_t)tap * 129 * 32 + f4];
    }
    if (tid >= 384 && tid < 512) {   // zero halo px columns 0,65 for all (ri, cc)
      int z = tid - 384;
      int ri = z >> 5, cc = (z >> 1) & 15, col = (z & 1) * 65;
      s[S_IN + (ri * 16 + cc) * 68 + col] = 0.f;
    }
    unsigned long long acc[2][4][2];   // [row][px][f-pair]
    {
      unsigned long long bp0 = pk2(b2[f0], b2[f0+1]);
      unsigned long long bp1 = pk2(b2[f0+2], b2[f0+3]);
#pragma unroll
      for (int r = 0; r < 2; r++)
#pragma unroll
        for (int i = 0; i < 4; i++) { acc[r][i][0] = bp0; acc[r][i][1] = bp1; }
    }
    __syncthreads();
    // time-channel contribution with border-valid tap masking
#pragma unroll
    for (int ky = 0; ky < 3; ky++) {
#pragma unroll
      for (int kx = 0; kx < 3; kx++) {
        ulonglong2 wp = *(const ulonglong2*)&s[S_WT + (ky * 3 + kx) * 128 + f0];
#pragma unroll
        for (int r = 0; r < 2; r++) {
          int grow = oy0 + r + ky - 1;
          if (grow >= 0 && grow < 64) {
#pragma unroll
            for (int i = 0; i < 4; i++) {
              int col = px0 + i + kx - 1;
              if (col >= 0 && col < 64) {
                acc[r][i][0] = fma2(td, wp.x, acc[r][i][0]);
                acc[r][i][1] = fma2(td, wp.y, acc[r][i][1]);
              }
            }
          }
        }
      }
    }
    // ---- stage A: conv2 over 8 chunks of 16 input channels ----
    for (int ch = 0; ch < 128; ch += 16) {
      __syncthreads();
      // input: 4 rows x 64 px x 16 ch; store transposed [ri][cc][68 px]
#pragma unroll
      for (int l = 0; l < 2; l++) {
        int idx = tid + l * NTHR;
        int ri = idx >> 8, px = (idx & 255) >> 2, q = idx & 3;
        int row = oy0 + ri - 1;
        float4 v = make_float4(0.f, 0.f, 0.f, 0.f);
        if (row >= 0 && row < 64)
          v = in4[((size_t)((b * 64 + row) * 64 + px)) * 32 + (ch >> 2) + q];
        float* bp = &s[S_IN + (ri * 16 + q * 4) * 68 + px + 1];
        bp[0] = v.x; bp[68] = v.y; bp[136] = v.z; bp[204] = v.w;
      }
      // weights: 9 taps x 16 ch x 128 f = 4608 float4
#pragma unroll
      for (int l = 0; l < 9; l++) {
        int idx = tid + l * NTHR;
        int tap = idx >> 9, rem = idx & 511, cc = rem >> 5, f4 = rem & 31;
        ((float4*)(s + S_W2))[(tap * 16 + cc) * 32 + f4] =
            w24[((size_t)tap * 129 + 1 + ch + cc) * 32 + f4];
      }
      __syncthreads();
      for (int cc = 0; cc < 16; cc++) {
        unsigned long long dv[4][6];
#pragma unroll
        for (int ri = 0; ri < 4; ri++) {
          const float* bp = &s[S_IN + (ri * 16 + cc) * 68 + px0];
          float4 a = *(const float4*)bp;
          float2 t2 = *(const float2*)(bp + 4);
          dv[ri][0] = dup2(a.x); dv[ri][1] = dup2(a.y);
          dv[ri][2] = dup2(a.z); dv[ri][3] = dup2(a.w);
          dv[ri][4] = dup2(t2.x); dv[ri][5] = dup2(t2.y);
        }
#pragma unroll
        for (int ky = 0; ky < 3; ky++) {
#pragma unroll
          for (int kx = 0; kx < 3; kx++) {
            ulonglong2 wv =
                *(const ulonglong2*)&s[S_W2 + ((ky * 3 + kx) * 16 + cc) * 128 + f0];
#pragma unroll
            for (int r = 0; r < 2; r++) {
#pragma unroll
              for (int i = 0; i < 4; i++) {
                unsigned long long a = dv[r + ky][i + kx];
                acc[r][i][0] = fma2(a, wv.x, acc[r][i][0]);
                acc[r][i][1] = fma2(a, wv.y, acc[r][i][1]);
              }
            }
          }
        }
      }
    }
    // ---- stage A epilogue: relu + store h2 tile to smem [px][136] ----
#pragma unroll
    for (int r = 0; r < 2; r++) {
#pragma unroll
      for (int i = 0; i < 4; i++) {
        int p_t = r * 64 + px0 + i;
#pragma unroll
        for (int j = 0; j < 2; j++) {
          float lo, hi;
          upk2(lo, hi, acc[r][i][j]);
          *(float2*)&s[S_H2 + p_t * 136 + f0 + 2*j] =
              make_float2(fmaxf(lo, 0.f), fmaxf(hi, 0.f));
        }
      }
    }
    __syncthreads();
    // ---- stage B: conv3 on the smem tile (k blocked by 4, vector a loads) ----
    unsigned long long accB[8];
    {
      unsigned long long bp = pk2(b3[f0c]   + tval * w3[f0c],
                                  b3[f0c+1] + tval * w3[f0c+1]);
#pragma unroll
      for (int i = 0; i < 8; i++) accB[i] = bp;
    }
#pragma unroll 2
    for (int k0 = 0; k0 < 128; k0 += 4) {
      float4 av[8];
#pragma unroll
      for (int i = 0; i < 8; i++)
        av[i] = *(const float4*)&s[S_H2 + (px0c + i) * 136 + k0];
#pragma unroll
      for (int kk = 0; kk < 4; kk++) {
        unsigned long long wv =
            *(const unsigned long long*)&s[S_W3 + (1 + k0 + kk) * 64 + f0c];
#pragma unroll
        for (int i = 0; i < 8; i++)
          accB[i] = fma2(dup2(((const float*)&av[i])[kk]), wv, accB[i]);
      }
    }
    // ---- fused dopri5 epilogue (float2 granularity) ----
    const size_t pxg0 = (size_t)(b * 64 + oy0) * 64;
    float2* out2 = (float2*)&g_k[kout][0];
    if (mode == 0) {
#pragma unroll
      for (int i = 0; i < 8; i++) {
        size_t off = (pxg0 + px0c + i) * 32 + (f0c >> 1);
        float klo, khi;
        upk2(klo, khi, accB[i]);
        out2[off] = make_float2(klo, khi);
        float sx = 0.f, sy = 0.f;
        if (nload > 0) { float2 v = p0[off]; sx = fmaf(cl0,v.x,sx); sy = fmaf(cl0,v.y,sy); }
        if (nload > 1) { float2 v = p1[off]; sx = fmaf(cl1,v.x,sx); sy = fmaf(cl1,v.y,sy); }
        if (nload > 2) { float2 v = p2[off]; sx = fmaf(cl2,v.x,sx); sy = fmaf(cl2,v.y,sy); }
        if (nload > 3) { float2 v = p3[off]; sx = fmaf(cl3,v.x,sx); sy = fmaf(cl3,v.y,sy); }
        sx = fmaf(cacc, klo, sx); sy = fmaf(cacc, khi, sy);
        float2 yv = y2[off];
        yt2[off] = make_float2(fmaf(hs,sx,yv.x), fmaf(hs,sy,yv.y));
      }
    } else {
      const float E1f = (float)( 71.0 / 57600.0);
      const float E3f = (float)(-71.0 / 16695.0);
      const float E4f = (float)( 71.0 / 1920.0);
      const float E5f = (float)(-17253.0 / 339200.0);
      const float E6f = (float)( 22.0 / 525.0);
      const float E7f = (float)(-1.0 / 40.0);
      const float2* q1 = p0;                      // k1 buffer (FSAL-indexed)
      const float2* q3 = (const float2*)g_k[2];
      const float2* q4 = (const float2*)g_k[3];
      const float2* q5 = (const float2*)g_k[4];
      const float2* q6 = (const float2*)g_k[5];
#pragma unroll
      for (int i = 0; i < 8; i++) {
        size_t off = (pxg0 + px0c + i) * 32 + (f0c >> 1);
        float klo, khi;
        upk2(klo, khi, accB[i]);
        out2[off] = make_float2(klo, khi);        // store k7 for FSAL reuse
        float2 v1 = q1[off], v3 = q3[off], v4 = q4[off], v5 = q5[off], v6 = q6[off];
        float2 a = y2[off], bb = yt2[off];        // yt holds y5
#define ECOMP(c, kacc) { \
        float e = hs * (E1f*v1.c + E3f*v3.c + E4f*v4.c + E5f*v5.c + E6f*v6.c + E7f*(kacc)); \
        float sc = 1e-3f + 1e-3f * fmaxf(fabsf(a.c), fabsf(bb.c)); \
        float rr = e / sc; local += (double)rr * (double)rr; }
        ECOMP(x, klo) ECOMP(y, khi)
#undef ECOMP
      }
    }
    __syncthreads();
  }
  ep += 256 + nb;
  if (mode == 1) {
    __syncthreads();
    s_red[tid] = local;
    __syncthreads();
    for (int o = 256; o > 0; o >>= 1) {
      if (tid < o) s_red[tid] += s_red[tid + o];
      __syncthreads();
    }
    if (tid == 0) atomicAdd(&g_sumsq[it], s_red[0]);
  }
}

// ---------------- FSAL stage-1 combine: yt = y + hs*(A21*k1) ----------------
__device__ void combine1_phase(float* __restrict__ yt, const float* __restrict__ y,
                               const float* __restrict__ k1, float hs, float A21,
                               unsigned int nb) {
  const float4* y4 = (const float4*)y;
  const float4* k4 = (const float4*)k1;
  float4* o4 = (float4*)yt;
  for (int i = blockIdx.x * NTHR + threadIdx.x; i < NV4; i += nb * NTHR) {
    float4 kv = k4[i], yv = y4[i];
    float sx = A21 * kv.x, sy = A21 * kv.y, sz = A21 * kv.z, sw = A21 * kv.w;
    o4[i] = make_float4(fmaf(hs,sx,yv.x), fmaf(hs,sy,yv.y),
                        fmaf(hs,sz,yv.z), fmaf(hs,sw,yv.w));
  }
}

// ---------------- output head: 1x1, 64 -> 10 ----------------
__device__ void head_phase(const float* __restrict__ y, const float* __restrict__ wo,
                           const float* __restrict__ bo, float* __restrict__ out,
                           float* s, unsigned int nb) {
  float* w_s = s;        // [64][10]
  float* b_s = s + 640;
  int tid = threadIdx.x;
  __syncthreads();
  for (int i = tid; i < 640; i += NTHR) w_s[i] = wo[i];
  if (tid < 10) b_s[tid] = bo[tid];
  __syncthreads();
  for (int p = blockIdx.x * NTHR + tid; p < PXTOT; p += nb * NTHR) {
    const float4* yp = (const float4*)(y + (size_t)p * 64);
    float o[10];
#pragma unroll
    for (int k = 0; k < 10; k++) o[k] = b_s[k];
#pragma unroll 4
    for (int c4 = 0; c4 < 16; c4++) {
      float4 v = yp[c4];
      int c = c4 * 4;
#pragma unroll
      for (int k = 0; k < 10; k++)
        o[k] += v.x * w_s[c*10+k] + v.y * w_s[(c+1)*10+k] +
                v.z * w_s[(c+2)*10+k] + v.w * w_s[(c+3)*10+k];
    }
#pragma unroll
    for (int k = 0; k < 10; k++) out[(size_t)p * 10 + k] = o[k];
  }
}

// ---------------- the persistent ODE kernel ----------------
__global__ void __launch_bounds__(NTHR, 1)
ode_k(const float* __restrict__ x,
      const float* __restrict__ w1, const float* __restrict__ b1,
      const float* __restrict__ w2, const float* __restrict__ b2,
      const float* __restrict__ w3, const float* __restrict__ b3,
      const float* __restrict__ wo, const float* __restrict__ bo,
      float* __restrict__ out) {
  extern __shared__ float s_mem[];
  __shared__ double s_red[NTHR];
  __shared__ int s_t;
  const unsigned int nb = gridDim.x;
  unsigned int bt = 0;
  unsigned int e1 = 0, e2 = 0;

  const float A21 = (float)(1.0/5.0);
  const float A31 = (float)(3.0/40.0),  A32 = (float)(9.0/40.0);
  const float A41 = (float)(44.0/45.0), A42 = (float)(-56.0/15.0), A43 = (float)(32.0/9.0);
  const float A51 = (float)(19372.0/6561.0), A52 = (float)(-25360.0/2187.0),
              A53 = (float)(64448.0/6561.0), A54 = (float)(-212.0/729.0);
  const float A61 = (float)(9017.0/3168.0), A62 = (float)(-355.0/33.0),
              A63 = (float)(46732.0/5247.0), A64 = (float)(49.0/176.0),
              A65 = (float)(-5103.0/18656.0);
  const float Bc1 = (float)(35.0/384.0), Bc3 = (float)(500.0/1113.0),
              Bc4 = (float)(125.0/192.0), Bc5 = (float)(-2187.0/6784.0),
              Bc6 = (float)(11.0/84.0);

  // y0 = x
  {
    float4* d = (float4*)g_buf0;
    const float4* sx = (const float4*)x;
    for (int i = blockIdx.x * NTHR + threadIdx.x; i < NV4; i += nb * NTHR) d[i] = sx[i];
  }
  gsync(bt, nb);

  float t = 0.0f, h = 0.1f;
  int cur = 0;
  int ik1 = 0, ik7 = 6;      // FSAL buffer indices for k1 / k7

  for (int it = 0; it < NITERS; it++) {
    if (t >= 1.0f) break;       // uniform across all blocks (replicated controller)
    float* y  = cur ? g_buf1 : g_buf0;
    float* yt = cur ? g_buf0 : g_buf1;
    const float hs = fminf(h, 1.0f - t);
    const float t2 = t + hs * 0.2f;
    const float t3 = t + hs * 0.3f;
    const float t4 = t + hs * 0.8f;
    const float t5 = t + hs * (8.0f / 9.0f);
    const float t6 = t + hs;

#define FEVAL(SRC, TV, KO, MODE, P0, P1, P2, P3, C0, C1, C2, C3, NL, CACC)      \
    do {                                                                        \
      conv1_phase((SRC), (TV), w1, b1, s_mem, e1, nb, &s_t); gsync(bt, nb);     \
      conv23_phase((TV), w2, b2, w3, b3, (KO), (MODE), (P0), (P1), (P2), (P3),  \
                   (C0), (C1), (C2), (C3), (NL), (CACC), y, yt, hs, it,         \
                   s_mem, s_red, e2, nb, &s_t);              gsync(bt, nb);     \
    } while (0)

    // stage 1: FSAL — k1 already in g_k[ik1] except on the very first iteration
    if (it == 0) {
      FEVAL(y,  t,  ik1, 0, g_k[0], g_k[0], g_k[0], g_k[0], 0,0,0,0,     0, A21);
    } else {
      combine1_phase(yt, y, g_k[ik1], hs, A21, nb);  gsync(bt, nb);
    }
    FEVAL(yt, t2, 1, 0, g_k[ik1], g_k[0],   g_k[0],  g_k[0],  A31,0,0,0,       1, A32);
    FEVAL(yt, t3, 2, 0, g_k[ik1], g_k[1],   g_k[0],  g_k[0],  A41,A42,0,0,     2, A43);
    FEVAL(yt, t4, 3, 0, g_k[ik1], g_k[1],   g_k[2],  g_k[0],  A51,A52,A53,0,   3, A54);
    FEVAL(yt, t5, 4, 0, g_k[ik1], g_k[1],   g_k[2],  g_k[3],  A61,A62,A63,A64, 4, A65);
    FEVAL(yt, t6, 5, 0, g_k[ik1], g_k[2],   g_k[3],  g_k[4],  Bc1,Bc3,Bc4,Bc5, 4, Bc6); // -> y5
    // stage 7 (err): stores k7 into g_k[ik7]; P0 carries k1 buffer for the E1 term
    FEVAL(yt, t6, ik7, 1, g_k[ik1], g_k[0], g_k[0],  g_k[0],  0,0,0,0,         0, 0.f);
#undef FEVAL

    // replicated controller
    double ss = g_sumsq[it];
    float en = sqrtf((float)(ss / (double)NY));
    int accept = (en <= 1.0f) ? 1 : 0;
    float ens = fmaxf(en, 1e-8f);
    float fac = fminf(fmaxf(0.9f * powf(ens, -0.2f), 0.2f), 10.0f);
    if (accept) {
      t = t + hs; cur ^= 1;
      int tmp = ik1; ik1 = ik7; ik7 = tmp;   // FSAL: k1 <- k7
    }
    h = fmaxf(hs * fac, 1e-4f);
  }

  const float* yfin = cur ? g_buf1 : g_buf0;
  head_phase(yfin, wo, bo, out, s_mem, nb);
}

// ---------------- launch: 2 graph nodes total ----------------
extern "C" void kernel_launch(void* const* d_in, const int* in_sizes, int n_in,
                              void* d_out, int out_size) {
  (void)in_sizes; (void)n_in; (void)out_size;
  const float* x  = (const float*)d_in[0];
  const float* w1 = (const float*)d_in[1];
  const float* b1 = (const float*)d_in[2];
  const float* w2 = (const float*)d_in[3];
  const float* b2 = (const float*)d_in[4];
  const float* w3 = (const float*)d_in[5];
  const float* b3 = (const float*)d_in[6];
  const float* wo = (const float*)d_in[7];
  const float* bo = (const float*)d_in[8];

  int dev = 0;
  cudaGetDevice(&dev);
  int nsm = 148;
  cudaDeviceGetAttribute(&nsm, cudaDevAttrMultiProcessorCount, dev);

  const int smem_bytes = S_TOT * 4;   // 198400 B
  cudaFuncSetAttribute(ode_k, cudaFuncAttributeMaxDynamicSharedMemorySize, smem_bytes);

  init_k<<<1, 1>>>();
  ode_k<<<nsm, NTHR, smem_bytes>>>(x, w1, b1, w2, b2, w3, b3, wo, bo, (float*)d_out);
}

// round 13
// speedup vs baseline: 2.3814x; 1.0352x over previous
#include <cuda_runtime.h>
#include <math.h>

// ---------------- problem dims ----------------
#define PXTOT 32768            // B*H*W = 8*64*64
#define NY    2097152          // PXTOT * 64
#define NH    4194304          // PXTOT * 128
#define NV4   (NY/4)
#define NITERS 32
#define NTHR  512
#define NPHASE 224             // max evals = 1 + 32*6 = 193

// ---------------- device state ----------------
__device__ float g_buf0[NY];       // y / ytmp ping-pong
__device__ float g_buf1[NY];
__device__ float g_k[7][NY];
__device__ float g_h1[NH];
__device__ double g_sumsq[NITERS];
__device__ unsigned int g_bar;
__device__ unsigned int g_tks[NPHASE];  // per-phase ticket counters
__device__ unsigned int g_f1[256];   // conv1 tile completion (eval number)
__device__ unsigned int g_f2[256];   // conv23 tile completion (eval number)

// ---------------- smem layout (floats) for the fused conv2+conv3 phase ------
#define S_IN  0                // 4*16*68      = 4352
#define S_W2  4352             // [9][16][128] = 18432
#define S_WT  22784            // [9][128]     = 1152
#define S_H2  23936            // [128][136]   = 17408
#define S_W3  41344            // [129][64]    = 8256
#define S_TOT 49600            // * 4 B = 198400 B

// ---------------- f32x2 helpers ----------------
__device__ __forceinline__ unsigned long long pk2(float lo, float hi) {
  unsigned long long r;
  asm("mov.b64 %0, {%1, %2};" : "=l"(r) : "f"(lo), "f"(hi));
  return r;
}
__device__ __forceinline__ unsigned long long dup2(float a) { return pk2(a, a); }
__device__ __forceinline__ unsigned long long fma2(unsigned long long a,
                                                   unsigned long long b,
                                                   unsigned long long c) {
  unsigned long long d;
  asm("fma.rn.f32x2 %0, %1, %2, %3;" : "=l"(d) : "l"(a), "l"(b), "l"(c));
  return d;
}
__device__ __forceinline__ void upk2(float& lo, float& hi, unsigned long long v) {
  asm("mov.b64 {%0, %1}, %2;" : "=f"(lo), "=f"(hi) : "l"(v));
}

// ---------------- init node ----------------
__global__ void init_k() {
  g_bar = 0u;
  for (int i = 0; i < NPHASE; i++) g_tks[i] = 0u;
  for (int i = 0; i < NITERS; i++) g_sumsq[i] = 0.0;
  for (int i = 0; i < 256; i++) { g_f1[i] = 0u; g_f2[i] = 0u; }
}

// ---------------- software grid barrier ----------------
__device__ __forceinline__ void gsync(unsigned int& bt, unsigned int nb) {
  __syncthreads();
  if (threadIdx.x == 0) {
    __threadfence();
    atomicAdd(&g_bar, 1u);
    bt += nb;
    while ((int)(*(volatile unsigned int*)&g_bar - bt) < 0) __nanosleep(32);
    __threadfence();
  }
  __syncthreads();
}

// ---------------- per-phase tile tickets ----------------
__device__ __forceinline__ int grab(unsigned int* ctr, int nt, int* s_t) {
  if (threadIdx.x == 0) {
    unsigned int tk = atomicAdd(ctr, 1u);
    int loc = (int)tk;
    *s_t = (loc >= 0 && loc < nt) ? loc : -1;
  }
  __syncthreads();
  int r = *s_t;
  __syncthreads();
  return r;
}

// ---------------- dataflow flags ----------------
// wait for flags f[b*32 + q], q in [plo,phi], to reach thr; acquire.
__device__ __forceinline__ void waitflags(unsigned int* f, int b, int plo, int phi,
                                          unsigned int thr) {
  if (threadIdx.x == 0) {
    for (int q = plo; q <= phi; q++) {
      volatile unsigned int* p = f + b * 32 + q;
      while (*p < thr) __nanosleep(20);
    }
    __threadfence();
  }
  __syncthreads();
}
// release: all tile work done -> publish eval number.
__device__ __forceinline__ void setflag(unsigned int* f, int idx, unsigned int v) {
  __syncthreads();
  if (threadIdx.x == 0) {
    __threadfence();
    *(volatile unsigned int*)(f + idx) = v;
  }
}

// ---------------- fused f-eval: one ticket stream, flag-synced ----------------
// tickets 0..255: conv1 tiles (128 px = 2 rows), 256..511: conv23 tiles (same idx).
__device__ void feval_phase(
    float tval,
    const float* __restrict__ in,                     // conv1 source
    const float* __restrict__ kcmb, float ccmb, int do_cmb,  // inline FSAL combine
    const float* __restrict__ w1, const float* __restrict__ b1,
    const float* __restrict__ w2, const float* __restrict__ b2,
    const float* __restrict__ w3, const float* __restrict__ b3,
    int kout, int mode,
    const float* kl0, const float* kl1, const float* kl2, const float* kl3,
    float cl0, float cl1, float cl2, float cl3, int nload, float cacc,
    const float* __restrict__ y, float* __restrict__ yt,
    float hs, int it,
    float* s, double* s_red, unsigned int ev,
    unsigned int nb, int* s_t) {
  const int tid = threadIdx.x;
  const float4* w14 = (const float4*)w1;
  const float4* w24 = (const float4*)w2;
  const float4* w34 = (const float4*)w3;
  const float4* in4c1 = (const float4*)in;
  const float4* kc4 = (const float4*)kcmb;
  const float4* h14 = (const float4*)g_h1;
  const float2* y2  = (const float2*)y;
  float2* yt2 = (float2*)yt;
  const float2* p0 = (const float2*)kl0;
  const float2* p1 = (const float2*)kl1;
  const float2* p2 = (const float2*)kl2;
  const float2* p3 = (const float2*)kl3;
  const unsigned long long td = dup2(tval);
  double local = 0.0;

  while (true) {
    int tk = grab(&g_tks[ev], 512, s_t);
    if (tk < 0) break;

    if (tk < 256) {
      // ================= conv1 tile =================
      const int j = tk, jb = j >> 5, jp = j & 31;
      // WAR/RAW: previous eval's conv23 consumers of our h1 rows / producers of yt,k
      waitflags(g_f2, jb, jp > 0 ? jp - 1 : 0, jp < 31 ? jp + 1 : 31, ev - 1);
      float* in_s = s;                 // [32 ch][132 px]
      float* w_s  = s + 4224;          // [32 ch][128 f]
      const int f0  = (tid & 31) * 4;
      const int px0 = (tid >> 5) * 8;
      const int pxbase = j * 128;
      unsigned long long acc[8][2];
      {
        unsigned long long bp0 = pk2(b1[f0]   + tval * w1[f0],
                                     b1[f0+1] + tval * w1[f0+1]);
        unsigned long long bp1 = pk2(b1[f0+2] + tval * w1[f0+2],
                                     b1[f0+3] + tval * w1[f0+3]);
#pragma unroll
        for (int i = 0; i < 8; i++) { acc[i][0] = bp0; acc[i][1] = bp1; }
      }
      for (int ch = 0; ch < 64; ch += 32) {
        __syncthreads();
#pragma unroll
        for (int l = 0; l < 2; l++) {
          int idx = tid + l * NTHR;
          int px = idx >> 3, c4 = idx & 7;
          size_t goff = (size_t)(pxbase + px) * 16 + (ch >> 2) + c4;
          float4 v = in4c1[goff];
          if (do_cmb) {      // v = y + hs*(ccmb*k1)  (two-op rounding = epilogue)
            float4 kv = kc4[goff];
            v.x = fmaf(hs, ccmb * kv.x, v.x);
            v.y = fmaf(hs, ccmb * kv.y, v.y);
            v.z = fmaf(hs, ccmb * kv.z, v.z);
            v.w = fmaf(hs, ccmb * kv.w, v.w);
          }
          in_s[(c4*4+0)*132 + px] = v.x; in_s[(c4*4+1)*132 + px] = v.y;
          in_s[(c4*4+2)*132 + px] = v.z; in_s[(c4*4+3)*132 + px] = v.w;
        }
#pragma unroll
        for (int l = 0; l < 2; l++) {
          int idx = tid + l * NTHR;
          int k = idx >> 5, f4 = idx & 31;
          ((float4*)w_s)[k * 32 + f4] = w14[(size_t)(1 + ch + k) * 32 + f4];
        }
        __syncthreads();
#pragma unroll 4
        for (int k = 0; k < 32; k++) {
          ulonglong2 wA = *(const ulonglong2*)&w_s[k*128 + f0];
          float4 a0 = *(const float4*)&in_s[k*132 + px0];
          float4 a1 = *(const float4*)&in_s[k*132 + px0 + 4];
          const float* ap = (const float*)&a0;
#pragma unroll
          for (int i = 0; i < 4; i++) {
            unsigned long long a = dup2(ap[i]);
            acc[i][0] = fma2(a, wA.x, acc[i][0]);
            acc[i][1] = fma2(a, wA.y, acc[i][1]);
          }
          const float* ap1 = (const float*)&a1;
#pragma unroll
          for (int i = 0; i < 4; i++) {
            unsigned long long a = dup2(ap1[i]);
            acc[4+i][0] = fma2(a, wA.x, acc[4+i][0]);
            acc[4+i][1] = fma2(a, wA.y, acc[4+i][1]);
          }
        }
      }
      float4* out4 = (float4*)g_h1;
#pragma unroll
      for (int i = 0; i < 8; i++) {
        float o[4];
        upk2(o[0], o[1], acc[i][0]); upk2(o[2], o[3], acc[i][1]);
#pragma unroll
        for (int jj = 0; jj < 4; jj++) o[jj] = fmaxf(o[jj], 0.f);
        out4[(size_t)(pxbase + px0 + i) * 32 + (f0 >> 2)] =
            make_float4(o[0], o[1], o[2], o[3]);
      }
      setflag(g_f1, j, ev);

    } else {
      // ================= conv23 tile =================
      const int blk = tk - 256;
      const int b   = blk >> 5;
      const int p   = blk & 31;
      const int oy0 = p * 2;
      waitflags(g_f1, b, p > 0 ? p - 1 : 0, p < 31 ? p + 1 : 31, ev);
      const int f0   = (tid & 31) * 4;
      const int px0  = (tid >> 5) * 4;
      const int f0c  = (tid & 31) * 2;
      const int px0c = (tid >> 5) * 8;
      // one-time per tile: w3, wt, halo zeros
#pragma unroll
      for (int l = 0; l < 5; l++) {
        int idx = tid + l * NTHR;
        if (idx < 2064) ((float4*)(s + S_W3))[idx] = w34[idx];
      }
      if (tid < 288) {
        int tap = tid >> 5, f4 = tid & 31;
        ((float4*)(s + S_WT))[tap * 32 + f4] = w24[(size_t)tap * 129 * 32 + f4];
      }
      if (tid >= 384 && tid < 512) {
        int z = tid - 384;
        int ri = z >> 5, cc = (z >> 1) & 15, col = (z & 1) * 65;
        s[S_IN + (ri * 16 + cc) * 68 + col] = 0.f;
      }
      unsigned long long acc[2][4][2];
      {
        unsigned long long bp0 = pk2(b2[f0], b2[f0+1]);
        unsigned long long bp1 = pk2(b2[f0+2], b2[f0+3]);
#pragma unroll
        for (int r = 0; r < 2; r++)
#pragma unroll
          for (int i = 0; i < 4; i++) { acc[r][i][0] = bp0; acc[r][i][1] = bp1; }
      }
      __syncthreads();
      // time-channel contribution with border-valid tap masking
#pragma unroll
      for (int ky = 0; ky < 3; ky++) {
#pragma unroll
        for (int kx = 0; kx < 3; kx++) {
          ulonglong2 wp = *(const ulonglong2*)&s[S_WT + (ky * 3 + kx) * 128 + f0];
#pragma unroll
          for (int r = 0; r < 2; r++) {
            int grow = oy0 + r + ky - 1;
            if (grow >= 0 && grow < 64) {
#pragma unroll
              for (int i = 0; i < 4; i++) {
                int col = px0 + i + kx - 1;
                if (col >= 0 && col < 64) {
                  acc[r][i][0] = fma2(td, wp.x, acc[r][i][0]);
                  acc[r][i][1] = fma2(td, wp.y, acc[r][i][1]);
                }
              }
            }
          }
        }
      }
      // stage A: conv2 over 8 chunks of 16 input channels
      for (int ch = 0; ch < 128; ch += 16) {
        __syncthreads();
#pragma unroll
        for (int l = 0; l < 2; l++) {
          int idx = tid + l * NTHR;
          int ri = idx >> 8, px = (idx & 255) >> 2, q = idx & 3;
          int row = oy0 + ri - 1;
          float4 v = make_float4(0.f, 0.f, 0.f, 0.f);
          if (row >= 0 && row < 64)
            v = h14[((size_t)((b * 64 + row) * 64 + px)) * 32 + (ch >> 2) + q];
          float* bp = &s[S_IN + (ri * 16 + q * 4) * 68 + px + 1];
          bp[0] = v.x; bp[68] = v.y; bp[136] = v.z; bp[204] = v.w;
        }
#pragma unroll
        for (int l = 0; l < 9; l++) {
          int idx = tid + l * NTHR;
          int tap = idx >> 9, rem = idx & 511, cc = rem >> 5, f4 = rem & 31;
          ((float4*)(s + S_W2))[(tap * 16 + cc) * 32 + f4] =
              w24[((size_t)tap * 129 + 1 + ch + cc) * 32 + f4];
        }
        __syncthreads();
        for (int cc = 0; cc < 16; cc++) {
          unsigned long long dv[4][6];
#pragma unroll
          for (int ri = 0; ri < 4; ri++) {
            const float* bp = &s[S_IN + (ri * 16 + cc) * 68 + px0];
            float4 a = *(const float4*)bp;
            float2 t2 = *(const float2*)(bp + 4);
            dv[ri][0] = dup2(a.x); dv[ri][1] = dup2(a.y);
            dv[ri][2] = dup2(a.z); dv[ri][3] = dup2(a.w);
            dv[ri][4] = dup2(t2.x); dv[ri][5] = dup2(t2.y);
          }
#pragma unroll
          for (int ky = 0; ky < 3; ky++) {
#pragma unroll
            for (int kx = 0; kx < 3; kx++) {
              ulonglong2 wv =
                  *(const ulonglong2*)&s[S_W2 + ((ky * 3 + kx) * 16 + cc) * 128 + f0];
#pragma unroll
              for (int r = 0; r < 2; r++) {
#pragma unroll
                for (int i = 0; i < 4; i++) {
                  unsigned long long a = dv[r + ky][i + kx];
                  acc[r][i][0] = fma2(a, wv.x, acc[r][i][0]);
                  acc[r][i][1] = fma2(a, wv.y, acc[r][i][1]);
                }
              }
            }
          }
        }
      }
      // stage A epilogue: relu + h2 tile to smem
#pragma unroll
      for (int r = 0; r < 2; r++) {
#pragma unroll
        for (int i = 0; i < 4; i++) {
          int p_t = r * 64 + px0 + i;
#pragma unroll
          for (int jj = 0; jj < 2; jj++) {
            float lo, hi;
            upk2(lo, hi, acc[r][i][jj]);
            *(float2*)&s[S_H2 + p_t * 136 + f0 + 2*jj] =
                make_float2(fmaxf(lo, 0.f), fmaxf(hi, 0.f));
          }
        }
      }
      __syncthreads();
      // stage B: conv3 on the smem tile
      unsigned long long accB[8];
      {
        unsigned long long bp = pk2(b3[f0c]   + tval * w3[f0c],
                                    b3[f0c+1] + tval * w3[f0c+1]);
#pragma unroll
        for (int i = 0; i < 8; i++) accB[i] = bp;
      }
#pragma unroll 2
      for (int k0 = 0; k0 < 128; k0 += 4) {
        float4 av[8];
#pragma unroll
        for (int i = 0; i < 8; i++)
          av[i] = *(const float4*)&s[S_H2 + (px0c + i) * 136 + k0];
#pragma unroll
        for (int kk = 0; kk < 4; kk++) {
          unsigned long long wv =
              *(const unsigned long long*)&s[S_W3 + (1 + k0 + kk) * 64 + f0c];
#pragma unroll
          for (int i = 0; i < 8; i++)
            accB[i] = fma2(dup2(((const float*)&av[i])[kk]), wv, accB[i]);
        }
      }
      // fused dopri5 epilogue (float2 granularity)
      const size_t pxg0 = (size_t)(b * 64 + oy0) * 64;
      float2* out2 = (float2*)&g_k[kout][0];
      if (mode == 0) {
#pragma unroll
        for (int i = 0; i < 8; i++) {
          size_t off = (pxg0 + px0c + i) * 32 + (f0c >> 1);
          float klo, khi;
          upk2(klo, khi, accB[i]);
          out2[off] = make_float2(klo, khi);
          float sx = 0.f, sy = 0.f;
          if (nload > 0) { float2 v = p0[off]; sx = fmaf(cl0,v.x,sx); sy = fmaf(cl0,v.y,sy); }
          if (nload > 1) { float2 v = p1[off]; sx = fmaf(cl1,v.x,sx); sy = fmaf(cl1,v.y,sy); }
          if (nload > 2) { float2 v = p2[off]; sx = fmaf(cl2,v.x,sx); sy = fmaf(cl2,v.y,sy); }
          if (nload > 3) { float2 v = p3[off]; sx = fmaf(cl3,v.x,sx); sy = fmaf(cl3,v.y,sy); }
          sx = fmaf(cacc, klo, sx); sy = fmaf(cacc, khi, sy);
          float2 yv = y2[off];
          yt2[off] = make_float2(fmaf(hs,sx,yv.x), fmaf(hs,sy,yv.y));
        }
      } else {
        const float E1f = (float)( 71.0 / 57600.0);
        const float E3f = (float)(-71.0 / 16695.0);
        const float E4f = (float)( 71.0 / 1920.0);
        const float E5f = (float)(-17253.0 / 339200.0);
        const float E6f = (float)( 22.0 / 525.0);
        const float E7f = (float)(-1.0 / 40.0);
        const float2* q1 = p0;                      // k1 buffer (FSAL-indexed)
        const float2* q3 = (const float2*)g_k[2];
        const float2* q4 = (const float2*)g_k[3];
        const float2* q5 = (const float2*)g_k[4];
        const float2* q6 = (const float2*)g_k[5];
#pragma unroll
        for (int i = 0; i < 8; i++) {
          size_t off = (pxg0 + px0c + i) * 32 + (f0c >> 1);
          float klo, khi;
          upk2(klo, khi, accB[i]);
          out2[off] = make_float2(klo, khi);        // store k7 for FSAL reuse
          float2 v1 = q1[off], v3 = q3[off], v4 = q4[off], v5 = q5[off], v6 = q6[off];
          float2 a = y2[off], bb = yt2[off];        // yt holds y5
#define ECOMP(c, kacc) { \
          float e = hs * (E1f*v1.c + E3f*v3.c + E4f*v4.c + E5f*v5.c + E6f*v6.c + E7f*(kacc)); \
          float sc = 1e-3f + 1e-3f * fmaxf(fabsf(a.c), fabsf(bb.c)); \
          float rr = e / sc; local += (double)rr * (double)rr; }
          ECOMP(x, klo) ECOMP(y, khi)
#undef ECOMP
        }
      }
      setflag(g_f2, blk, ev);
    }
  }

  if (mode == 1) {
    __syncthreads();
    s_red[tid] = local;
    __syncthreads();
    for (int o = 256; o > 0; o >>= 1) {
      if (tid < o) s_red[tid] += s_red[tid + o];
      __syncthreads();
    }
    if (tid == 0) atomicAdd(&g_sumsq[it], s_red[0]);
  }
}

// ---------------- output head: 1x1, 64 -> 10 ----------------
__device__ void head_phase(const float* __restrict__ y, const float* __restrict__ wo,
                           const float* __restrict__ bo, float* __restrict__ out,
                           float* s, unsigned int nb) {
  float* w_s = s;        // [64][10]
  float* b_s = s + 640;
  int tid = threadIdx.x;
  __syncthreads();
  for (int i = tid; i < 640; i += NTHR) w_s[i] = wo[i];
  if (tid < 10) b_s[tid] = bo[tid];
  __syncthreads();
  for (int p = blockIdx.x * NTHR + tid; p < PXTOT; p += nb * NTHR) {
    const float4* yp = (const float4*)(y + (size_t)p * 64);
    float o[10];
#pragma unroll
    for (int k = 0; k < 10; k++) o[k] = b_s[k];
#pragma unroll 4
    for (int c4 = 0; c4 < 16; c4++) {
      float4 v = yp[c4];
      int c = c4 * 4;
#pragma unroll
      for (int k = 0; k < 10; k++)
        o[k] += v.x * w_s[c*10+k] + v.y * w_s[(c+1)*10+k] +
                v.z * w_s[(c+2)*10+k] + v.w * w_s[(c+3)*10+k];
    }
#pragma unroll
    for (int k = 0; k < 10; k++) out[(size_t)p * 10 + k] = o[k];
  }
}

// ---------------- the persistent ODE kernel ----------------
__global__ void __launch_bounds__(NTHR, 1)
ode_k(const float* __restrict__ x,
      const float* __restrict__ w1, const float* __restrict__ b1,
      const float* __restrict__ w2, const float* __restrict__ b2,
      const float* __restrict__ w3, const float* __restrict__ b3,
      const float* __restrict__ wo, const float* __restrict__ bo,
      float* __restrict__ out) {
  extern __shared__ float s_mem[];
  __shared__ double s_red[NTHR];
  __shared__ int s_t;
  const unsigned int nb = gridDim.x;
  unsigned int bt = 0;
  unsigned int ev = 0;

  const float A21 = (float)(1.0/5.0);
  const float A31 = (float)(3.0/40.0),  A32 = (float)(9.0/40.0);
  const float A41 = (float)(44.0/45.0), A42 = (float)(-56.0/15.0), A43 = (float)(32.0/9.0);
  const float A51 = (float)(19372.0/6561.0), A52 = (float)(-25360.0/2187.0),
              A53 = (float)(64448.0/6561.0), A54 = (float)(-212.0/729.0);
  const float A61 = (float)(9017.0/3168.0), A62 = (float)(-355.0/33.0),
              A63 = (float)(46732.0/5247.0), A64 = (float)(49.0/176.0),
              A65 = (float)(-5103.0/18656.0);
  const float Bc1 = (float)(35.0/384.0), Bc3 = (float)(500.0/1113.0),
              Bc4 = (float)(125.0/192.0), Bc5 = (float)(-2187.0/6784.0),
              Bc6 = (float)(11.0/84.0);

  // y0 = x
  {
    float4* d = (float4*)g_buf0;
    const float4* sx = (const float4*)x;
    for (int i = blockIdx.x * NTHR + threadIdx.x; i < NV4; i += nb * NTHR) d[i] = sx[i];
  }
  gsync(bt, nb);

  float t = 0.0f, h = 0.1f;
  int cur = 0;
  int ik1 = 0, ik7 = 6;      // FSAL buffer indices for k1 / k7

  for (int it = 0; it < NITERS; it++) {
    if (t >= 1.0f) break;       // uniform across all blocks (replicated controller)
    float* y  = cur ? g_buf1 : g_buf0;
    float* yt = cur ? g_buf0 : g_buf1;
    const float hs = fminf(h, 1.0f - t);
    const float t2 = t + hs * 0.2f;
    const float t3 = t + hs * 0.3f;
    const float t4 = t + hs * 0.8f;
    const float t5 = t + hs * (8.0f / 9.0f);
    const float t6 = t + hs;

#define FEVAL(SRC, KC, CC, DC, TV, KO, MODE, P0, P1, P2, P3, C0, C1, C2, C3, NL, CACC) \
    do {                                                                        \
      ev++;                                                                     \
      feval_phase((TV), (SRC), (KC), (CC), (DC), w1, b1, w2, b2, w3, b3,        \
                  (KO), (MODE), (P0), (P1), (P2), (P3),                         \
                  (C0), (C1), (C2), (C3), (NL), (CACC), y, yt, hs, it,          \
                  s_mem, s_red, ev, nb, &s_t);                                  \
    } while (0)

    // stage 1 (it==0 only): computes k1; epilogue yt unused (stage 2 inlines)
    if (it == 0) {
      FEVAL(y, y, 0.f, 0, t, ik1, 0, g_k[0], g_k[0], g_k[0], g_k[0],
            0,0,0,0, 0, A21);
    }
    // stage 2: conv1 inlines yt = y + hs*(A21*k1)  (FSAL)
    FEVAL(y, g_k[ik1], A21, 1, t2, 1, 0, g_k[ik1], g_k[0], g_k[0], g_k[0],
          A31,0,0,0, 1, A32);
    FEVAL(yt, y, 0.f, 0, t3, 2, 0, g_k[ik1], g_k[1], g_k[0], g_k[0],
          A41,A42,0,0, 2, A43);
    FEVAL(yt, y, 0.f, 0, t4, 3, 0, g_k[ik1], g_k[1], g_k[2], g_k[0],
          A51,A52,A53,0, 3, A54);
    FEVAL(yt, y, 0.f, 0, t5, 4, 0, g_k[ik1], g_k[1], g_k[2], g_k[3],
          A61,A62,A63,A64, 4, A65);
    FEVAL(yt, y, 0.f, 0, t6, 5, 0, g_k[ik1], g_k[2], g_k[3], g_k[4],
          Bc1,Bc3,Bc4,Bc5, 4, Bc6);                      // -> y5
    // stage 7 (err): stores k7 for FSAL; P0 carries k1 buffer for the E1 term
    FEVAL(yt, y, 0.f, 0, t6, ik7, 1, g_k[ik1], g_k[0], g_k[0], g_k[0],
          0,0,0,0, 0, 0.f);
#undef FEVAL

    gsync(bt, nb);

    // replicated controller
    double ss = g_sumsq[it];
    float en = sqrtf((float)(ss / (double)NY));
    int accept = (en <= 1.0f) ? 1 : 0;
    float ens = fmaxf(en, 1e-8f);
    float fac = fminf(fmaxf(0.9f * powf(ens, -0.2f), 0.2f), 10.0f);
    if (accept) {
      t = t + hs; cur ^= 1;
      int tmp = ik1; ik1 = ik7; ik7 = tmp;   // FSAL: k1 <- k7
    }
    h = fmaxf(hs * fac, 1e-4f);
  }

  const float* yfin = cur ? g_buf1 : g_buf0;
  head_phase(yfin, wo, bo, out, s_mem, nb);
}

// ---------------- launch: 2 graph nodes total ----------------
extern "C" void kernel_launch(void* const* d_in, const int* in_sizes, int n_in,
                              void* d_out, int out_size) {
  (void)in_sizes; (void)n_in; (void)out_size;
  const float* x  = (const float*)d_in[0];
  const float* w1 = (const float*)d_in[1];
  const float* b1 = (const float*)d_in[2];
  const float* w2 = (const float*)d_in[3];
  const float* b2 = (const float*)d_in[4];
  const float* w3 = (const float*)d_in[5];
  const float* b3 = (const float*)d_in[6];
  const float* wo = (const float*)d_in[7];
  const float* bo = (const float*)d_in[8];

  int dev = 0;
  cudaGetDevice(&dev);
  int nsm = 148;
  cudaDeviceGetAttribute(&nsm, cudaDevAttrMultiProcessorCount, dev);

  const int smem_bytes = S_TOT * 4;   // 198400 B
  cudaFuncSetAttribute(ode_k, cudaFuncAttributeMaxDynamicSharedMemorySize, smem_bytes);

  init_k<<<1, 1>>>();
  ode_k<<<nsm, NTHR, smem_bytes>>>(x, w1, b1, w2, b2, w3, b3, wo, bo, (float*)d_out);
}